// round 13
// baseline (speedup 1.0000x reference)
#include <cuda_runtime.h>
#include <math.h>

#define BB 16
#define NN 4096
#define DD 64
#define KK 8
#define HH 4
#define EPSF 1e-5f
// 16 * (-0.5 * 64 * ln(2*pi))
#define LOGPI_SUM (-940.99305800158484f)

typedef unsigned long long ull;

// ---------------- packed f32x2 helpers --------------------------------------
__device__ __forceinline__ ull pk2(float x, float y) {
    ull r; asm("mov.b64 %0, {%1, %2};" : "=l"(r) : "f"(x), "f"(y)); return r;
}
__device__ __forceinline__ void fma2(ull& d, ull a, ull b) {
    asm("fma.rn.f32x2 %0, %1, %2, %0;" : "+l"(d) : "l"(a), "l"(b));
}
__device__ __forceinline__ ull fma2r(ull a, ull b, ull c) {
    ull d; asm("fma.rn.f32x2 %0, %1, %2, %3;" : "=l"(d) : "l"(a), "l"(b), "l"(c)); return d;
}
__device__ __forceinline__ ull mul2(ull a, ull b) {
    ull d; asm("mul.rn.f32x2 %0, %1, %2;" : "=l"(d) : "l"(a), "l"(b)); return d;
}
union F4U { float4 v; ull u[2]; float s[4]; };

// ---------------- scratch (static device memory) ---------------------------
__device__ float g_x[BB * NN * DD];
__device__ float g_keys[(size_t)BB * NN * KK * DD];    // [b][n][k][d]
__device__ float g_slots[BB * KK * DD];
__device__ float g_sigma[BB * KK * DD];
__device__ float g_a[BB * KK * DD];     // -0.5/(sigma^2+eps)
__device__ float g_bq[BB * KK * DD];    // q/(sigma^2+eps)
__device__ float g_C[BB * KK * HH];     // logit bias per (b,k,h)
__device__ float g_A[BB * KK * HH];     // sum attn
__device__ float g_S2[BB * KK * DD];    // sum attn*k^2
__device__ float g_T[BB * KK * HH * DD];// sum attn*x  [b][k][h][e]

// ---------------- init + first-iteration coefficients ----------------------
__global__ void k_init_pre(const float* __restrict__ mu, const float* __restrict__ ls,
                           const float* __restrict__ mix0, const float* __restrict__ noise,
                           const float* __restrict__ tq, const float* __restrict__ gsl,
                           const float* __restrict__ bsl) {
    int bk = blockIdx.x, k = bk & (KK - 1);
    int d = threadIdx.x, h = d >> 4;
    __shared__ float sh[64];
    float sg = expf(ls[k * 64 + d]);
    float slot = mu[k * 64 + d] + sg * noise[bk * 64 + d];
    g_sigma[bk * 64 + d] = sg;
    g_slots[bk * 64 + d] = slot;
    sh[d] = slot;
    __syncthreads();
    float m = 0.f, q = 0.f;
#pragma unroll
    for (int j = 0; j < 64; j++) { float v = sh[j]; m += v; q += v * v; }
    m *= (1.f / 64.f);
    float var = q * (1.f / 64.f) - m * m;
    float sln = (slot - m) * rsqrtf(var + EPSF) * gsl[d] + bsl[d];
    float qd = sln * tq[((size_t)k * 64 + d) * 64 + d];
    float invden = 1.f / (sg * sg + EPSF);
    g_a[bk * 64 + d] = -0.5f * invden;
    g_bq[bk * 64 + d] = qd * invden;
    float cp = -logf(fmaxf(sg, EPSF)) - 0.5f * qd * qd * invden;
#pragma unroll
    for (int o = 1; o < 16; o <<= 1) cp += __shfl_xor_sync(0xffffffffu, cp, o);
    if ((d & 15) == 0) g_C[bk * 4 + h] = logf(mix0[k] + EPSF) + LOGPI_SUM + cp;
    g_S2[bk * 64 + d] = 0.f;
    if (d < 4) g_A[bk * 4 + d] = 0.f;
#pragma unroll
    for (int i = 0; i < 4; i++) g_T[bk * 256 + i * 64 + d] = 0.f;
}

// ---------------- LayerNorm of embeddings (warp per row) -------------------
__global__ void k_ln(const float* __restrict__ emb, const float* __restrict__ g,
                     const float* __restrict__ bt) {
    int row = blockIdx.x * 8 + (threadIdx.x >> 5);
    int lane = threadIdx.x & 31;
    float2 v = ((const float2*)emb)[(size_t)row * 32 + lane];
    float s = v.x + v.y, q = v.x * v.x + v.y * v.y;
#pragma unroll
    for (int o = 16; o; o >>= 1) {
        s += __shfl_xor_sync(0xffffffffu, s, o);
        q += __shfl_xor_sync(0xffffffffu, q, o);
    }
    float m = s * (1.f / 64.f);
    float var = q * (1.f / 64.f) - m * m;
    float r = rsqrtf(var + EPSF);
    float2 o;
    o.x = (v.x - m) * r * g[2 * lane] + bt[2 * lane];
    o.y = (v.y - m) * r * g[2 * lane + 1] + bt[2 * lane + 1];
    ((float2*)g_x)[(size_t)row * 32 + lane] = o;
}

// ---------------- keys GEMM: (b, ntile) blocks, k-loop, 8n x 8d (R6) --------
__global__ __launch_bounds__(128, 4) void k_keys(const float* __restrict__ tk) {
    __shared__ float xs[64 * 128];   // [e][n]  32 KB (transposed)
    __shared__ float ws[64 * 64];    // [e][d]  16 KB
    int b = blockIdx.x >> 5;
    int n0 = (blockIdx.x & 31) << 7;
    int t = threadIdx.x;
    {
        const float4* xg = (const float4*)(g_x + ((size_t)b * NN + n0) * 64);
#pragma unroll
        for (int r = 0; r < 16; r++) {
            int idx = t + r * 128;
            int n = idx & 127, e4 = idx >> 7;
            float4 v = xg[n * 16 + e4];
            int e0 = e4 << 2;
            xs[(e0 + 0) * 128 + n] = v.x;
            xs[(e0 + 1) * 128 + n] = v.y;
            xs[(e0 + 2) * 128 + n] = v.z;
            xs[(e0 + 3) * 128 + n] = v.w;
        }
    }
    int tx = t & 7, ty = t >> 3;
    int d0 = tx << 3;     // 0..56
    int nr = ty << 3;     // 0..120
    for (int k = 0; k < KK; k++) {
        __syncthreads();
        const float4* wg = (const float4*)(tk + (size_t)k * 4096);
#pragma unroll
        for (int r = 0; r < 8; r++)
            ((float4*)ws)[t + r * 128] = wg[t + r * 128];
        __syncthreads();
        ull acc[8][4];
#pragma unroll
        for (int n = 0; n < 8; n++)
#pragma unroll
            for (int p = 0; p < 4; p++) acc[n][p] = 0ull;
#pragma unroll 8
        for (int e = 0; e < 64; e++) {
            F4U wa; wa.v = *(const float4*)&ws[e * 64 + d0];
            F4U wb; wb.v = *(const float4*)&ws[e * 64 + d0 + 4];
            F4U xa; xa.v = *(const float4*)&xs[e * 128 + nr];
            F4U xb; xb.v = *(const float4*)&xs[e * 128 + nr + 4];
#pragma unroll
            for (int n = 0; n < 8; n++) {
                float xv = (n < 4) ? xa.s[n] : xb.s[n - 4];
                ull x2 = pk2(xv, xv);
                fma2(acc[n][0], x2, wa.u[0]);
                fma2(acc[n][1], x2, wa.u[1]);
                fma2(acc[n][2], x2, wb.u[0]);
                fma2(acc[n][3], x2, wb.u[1]);
            }
        }
        size_t o0 = (((size_t)b * NN + n0 + nr) * KK + k) * 64 + d0;
#pragma unroll
        for (int n = 0; n < 8; n++) {
            F4U oa, ob;
            oa.u[0] = acc[n][0]; oa.u[1] = acc[n][1];
            ob.u[0] = acc[n][2]; ob.u[1] = acc[n][3];
            *(float4*)&g_keys[o0 + (size_t)n * 512]     = oa.v;
            *(float4*)&g_keys[o0 + (size_t)n * 512 + 4] = ob.v;
        }
    }
}

// ---------------- fused attention pass (R6 structure, no prefetch, 3 blk/SM)
__global__ __launch_bounds__(256, 3) void k_pass(float* __restrict__ attn_out, int last) {
    __shared__ float4 xs[2048];       // [n][e/4]  32 KB
    __shared__ float attn_s[4096];    // [n][kh]   16 KB (reused as reduction scratch)
    int b = blockIdx.x >> 5;
    int n0 = (blockIdx.x & 31) << 7;
    int t = threadIdx.x, w = t >> 5, lane = t & 31;
    int bk = b * KK + (lane >> 2);
    int h = lane & 3;
    F4U a4[4], b4[4];
#pragma unroll
    for (int i = 0; i < 4; i++) {
        a4[i].v = *(const float4*)&g_a[bk * 64 + h * 16 + i * 4];
        b4[i].v = *(const float4*)&g_bq[bk * 64 + h * 16 + i * 4];
    }
    float C = g_C[bk * 4 + h];
    for (int i = t; i < 2048; i += 256)
        xs[i] = ((const float4*)g_x)[((size_t)b * NN + n0) * 16 + i];
    __syncthreads();

    F4U S2a[4];
#pragma unroll
    for (int j = 0; j < 4; j++) { S2a[j].u[0] = 0ull; S2a[j].u[1] = 0ull; }
    float Aacc = 0.f;
    float* aout = attn_out + (size_t)bk * NN * 4 + h;
    const float4* kbase = ((const float4*)g_keys) + ((size_t)b * NN + n0) * 128 + lane * 4;

    for (int ni = 0; ni < 16; ni++) {
        int nl = w * 16 + ni;
        const float4* kp = kbase + (size_t)nl * 128;
        F4U q0, q1, q2, q3;
        q0.v = kp[0]; q1.v = kp[1]; q2.v = kp[2]; q3.v = kp[3];
        ull kp8[8] = {q0.u[0], q0.u[1], q1.u[0], q1.u[1],
                      q2.u[0], q2.u[1], q3.u[0], q3.u[1]};
        ull lgp = 0ull;
#pragma unroll
        for (int j = 0; j < 8; j++) {
            ull tmp = fma2r(kp8[j], a4[j >> 1].u[j & 1], b4[j >> 1].u[j & 1]);
            lgp = fma2r(kp8[j], tmp, lgp);
        }
        F4U lgu; lgu.u[0] = lgp;
        float lg = C + lgu.s[0] + lgu.s[1];
        float mm = lg;
        mm = fmaxf(mm, __shfl_xor_sync(0xffffffffu, mm, 4));
        mm = fmaxf(mm, __shfl_xor_sync(0xffffffffu, mm, 8));
        mm = fmaxf(mm, __shfl_xor_sync(0xffffffffu, mm, 16));
        float ex = __expf(lg - mm);
        float ss = ex;
        ss += __shfl_xor_sync(0xffffffffu, ss, 4);
        ss += __shfl_xor_sync(0xffffffffu, ss, 8);
        ss += __shfl_xor_sync(0xffffffffu, ss, 16);
        float attn = __fdividef(ex, ss) + EPSF;
        attn_s[nl * 32 + lane] = attn;
        if (last) aout[(size_t)(n0 + nl) * 4] = attn;
        Aacc += attn;
        ull attn2 = pk2(attn, attn);
#pragma unroll
        for (int j = 0; j < 8; j++) {
            ull ak = mul2(attn2, kp8[j]);
            S2a[j >> 1].u[j & 1] = fma2r(ak, kp8[j], S2a[j >> 1].u[j & 1]);
        }
    }
    __syncthreads();

    // ---- phase 2: T[kh][e0..e0+7] = sum_n attn[n][kh] * x[n][e] -------------
    {
        int kh = t >> 3, et = t & 7;
        ull Tl[4] = {0ull, 0ull, 0ull, 0ull};
        const float* ap = attn_s + kh;
        const float4* xp = xs + et * 2;
#pragma unroll 4
        for (int n = 0; n < 128; n++) {
            float at = ap[n * 32];
            ull at2 = pk2(at, at);
            F4U xa; xa.v = xp[n * 16];
            F4U xb; xb.v = xp[n * 16 + 1];
            Tl[0] = fma2r(at2, xa.u[0], Tl[0]);
            Tl[1] = fma2r(at2, xa.u[1], Tl[1]);
            Tl[2] = fma2r(at2, xb.u[0], Tl[2]);
            Tl[3] = fma2r(at2, xb.u[1], Tl[3]);
        }
        int k2 = kh >> 2, h2 = kh & 3;
        float* gp = &g_T[(size_t)(b * KK + k2) * 256 + h2 * 64 + et * 8];
        F4U o0, o1;
        o0.u[0] = Tl[0]; o0.u[1] = Tl[1];
        o1.u[0] = Tl[2]; o1.u[1] = Tl[3];
#pragma unroll
        for (int j = 0; j < 4; j++) atomicAdd(gp + j, o0.s[j]);
#pragma unroll
        for (int j = 0; j < 4; j++) atomicAdd(gp + 4 + j, o1.s[j]);
    }

    // ---- S2 + A tree (reuse attn_s as scratch) ------------------------------
    __syncthreads();
    float* redf = attn_s;
#define SIDX(ww, j) ((ww) * 544 + lane * 17 + (j))
    if (w >= 4) {
#pragma unroll
        for (int j = 0; j < 16; j++) redf[SIDX(w - 4, j)] = S2a[j >> 2].s[j & 3];
        redf[SIDX(w - 4, 16)] = Aacc;
    }
    __syncthreads();
    if (w < 4) {
#pragma unroll
        for (int j = 0; j < 16; j++) S2a[j >> 2].s[j & 3] += redf[SIDX(w, j)];
        Aacc += redf[SIDX(w, 16)];
    }
    __syncthreads();
    if (w == 2 || w == 3) {
#pragma unroll
        for (int j = 0; j < 16; j++) redf[SIDX(w - 2, j)] = S2a[j >> 2].s[j & 3];
        redf[SIDX(w - 2, 16)] = Aacc;
    }
    __syncthreads();
    if (w < 2) {
#pragma unroll
        for (int j = 0; j < 16; j++) S2a[j >> 2].s[j & 3] += redf[SIDX(w, j)];
        Aacc += redf[SIDX(w, 16)];
    }
    __syncthreads();
    if (w == 1) {
#pragma unroll
        for (int j = 0; j < 16; j++) redf[SIDX(0, j)] = S2a[j >> 2].s[j & 3];
        redf[SIDX(0, 16)] = Aacc;
    }
    __syncthreads();
    if (w == 0) {
#pragma unroll
        for (int j = 0; j < 16; j++)
            atomicAdd(&g_S2[(size_t)b * 512 + lane * 16 + j],
                      S2a[j >> 2].s[j & 3] + redf[SIDX(0, j)]);
        atomicAdd(&g_A[b * 32 + lane], Aacc + redf[SIDX(0, 16)]);
    }
}

// ---------------- slot update + fused next-iter pre (128 threads, R6) ------
__global__ __launch_bounds__(128) void k_upd(
        const float* __restrict__ tk, const float* __restrict__ tv,
        const float* __restrict__ wih, const float* __restrict__ whh,
        const float* __restrict__ bih, const float* __restrict__ bhh,
        const float* __restrict__ w1, const float* __restrict__ b1,
        const float* __restrict__ w2, const float* __restrict__ b2,
        const float* __restrict__ gff, const float* __restrict__ bff,
        const float* __restrict__ tq, const float* __restrict__ gsl,
        const float* __restrict__ bsl,
        const float* __restrict__ noisef, float* __restrict__ out_slots, int last) {
    int bk = blockIdx.x;
    int k = bk & (KK - 1);
    int t = threadIdx.x;
    int d = t & 63, half = t >> 6;
    int h = d >> 4;
    __shared__ float Wt[24576];      // 96 KB, reused: gates -> w1T -> w2T
    __shared__ float Tsh[4][64], Ash[4];
    __shared__ float pu[2][64], ps1[2][64];
    __shared__ float ush[64], hsh[64];
    __shared__ float gsh[6][64];
    __shared__ float sh[64], presh[64], h1sh[256], pw2[2][64], osh[64];

    for (int idx = t; idx < 384; idx += 128) {
        int s = idx >= 192;
        int row = idx - s * 192;
        const float4* src = (const float4*)((s ? whh : wih) + (size_t)row * 64);
        float* dst = Wt + s * 12288 + row;
#pragma unroll
        for (int r = 0; r < 16; r++) {
            float4 v = src[r];
            dst[(4 * r + 0) * 192] = v.x;
            dst[(4 * r + 1) * 192] = v.y;
            dst[(4 * r + 2) * 192] = v.z;
            dst[(4 * r + 3) * 192] = v.w;
        }
    }
    for (int i = t; i < 256; i += 128) Tsh[i >> 6][i & 63] = g_T[bk * 256 + i];
    if (t < 4) Ash[t] = g_A[bk * 4 + t];
    if (t >= 64) hsh[d] = g_slots[bk * 64 + d];
    __syncthreads();
    float Nk = Ash[0] + Ash[1] + Ash[2] + Ash[3];
    {
        float u = 0.f, s1 = 0.f;
        int e0 = half * 32;
#pragma unroll 8
        for (int e = e0; e < e0 + 32; e++) {
            float tvv = Tsh[h][e];
            u  = fmaf(tvv, tv[((size_t)k * 64 + e) * 64 + d], u);
            s1 = fmaf(tvv, tk[((size_t)k * 64 + e) * 64 + d], s1);
        }
        pu[half][d] = u; ps1[half][d] = s1;
    }
    __syncthreads();
    float sigma_d = 0.f, u = 0.f;
    if (t < 64) {
        u = pu[0][d] + pu[1][d];
        float s1 = ps1[0][d] + ps1[1][d];
        float invNk = 1.f / Nk;
        u *= (invNk + EPSF);
        float sig2 = fmaxf(g_S2[bk * 64 + d] - 2.f * u * s1 + u * u * Ash[h], 0.f);
        sigma_d = sqrtf(sig2 * invNk) + EPSF;
        g_sigma[bk * 64 + d] = sigma_d;
        ush[d] = u;
    }
    __syncthreads();
    {
        const float* bi = half ? bhh : bih;
        const float* vi = half ? hsh : ush;
        const float* Wb = Wt + half * 12288;
        float g0 = bi[d], g1 = bi[64 + d], g2 = bi[128 + d];
#pragma unroll 8
        for (int e = 0; e < 64; e++) {
            float v = vi[e];
            g0 = fmaf(v, Wb[e * 192 + d], g0);
            g1 = fmaf(v, Wb[e * 192 + 64 + d], g1);
            g2 = fmaf(v, Wb[e * 192 + 128 + d], g2);
        }
        gsh[half * 3 + 0][d] = g0;
        gsh[half * 3 + 1][d] = g1;
        gsh[half * 3 + 2][d] = g2;
    }
    __syncthreads();
    float snew = 0.f;
    if (t < 64) {
        float r = 1.f / (1.f + expf(-(gsh[0][d] + gsh[3][d])));
        float z = 1.f / (1.f + expf(-(gsh[1][d] + gsh[4][d])));
        float nn2 = tanhf(gsh[2][d] + r * gsh[5][d]);
        snew = (1.f - z) * nn2 + z * hsh[d];
        sh[d] = snew;
    }
    for (int idx = t; idx < 256; idx += 128) {
        const float4* src = (const float4*)(w1 + (size_t)idx * 64);
        float* dst = Wt + idx;
#pragma unroll
        for (int r = 0; r < 16; r++) {
            float4 v = src[r];
            dst[(4 * r + 0) * 256] = v.x;
            dst[(4 * r + 1) * 256] = v.y;
            dst[(4 * r + 2) * 256] = v.z;
            dst[(4 * r + 3) * 256] = v.w;
        }
    }
    __syncthreads();
    if (t < 64) {
        float m = 0.f, qq = 0.f;
#pragma unroll
        for (int j = 0; j < 64; j++) { float v = sh[j]; m += v; qq += v * v; }
        m *= (1.f / 64.f);
        float var = qq * (1.f / 64.f) - m * m;
        presh[d] = (snew - m) * rsqrtf(var + EPSF) * gff[d] + bff[d];
    }
    __syncthreads();
    for (int j = t; j < 256; j += 128) {
        float acc = b1[j];
#pragma unroll 8
        for (int e = 0; e < 64; e++) acc = fmaf(presh[e], Wt[e * 256 + j], acc);
        h1sh[j] = fmaxf(acc, 0.f);
    }
    __syncthreads();
    for (int uu = t; uu < 256; uu += 128) {
        int row = uu & 63, q = uu >> 6;
        const float4* src = (const float4*)(w2 + (size_t)row * 256 + q * 64);
        float* dst = Wt + row;
#pragma unroll
        for (int r = 0; r < 16; r++) {
            float4 v = src[r];
            dst[(q * 64 + 4 * r + 0) * 64] = v.x;
            dst[(q * 64 + 4 * r + 1) * 64] = v.y;
            dst[(q * 64 + 4 * r + 2) * 64] = v.z;
            dst[(q * 64 + 4 * r + 3) * 64] = v.w;
        }
    }
    __syncthreads();
    {
        float o = 0.f;
        int j0 = half * 128;
#pragma unroll 8
        for (int j = j0; j < j0 + 128; j++) o = fmaf(h1sh[j], Wt[j * 64 + d], o);
        pw2[half][d] = o;
    }
    __syncthreads();
    if (t < 64) {
        float o = sh[d] + b2[d] + pw2[0][d] + pw2[1][d];
        g_slots[bk * 64 + d] = o;
        if (last) out_slots[bk * 64 + d] = o + sigma_d * noisef[bk * 64 + d];
        osh[d] = o;
    }
    __syncthreads();
    if (!last) {
        if (t < 64) {
            float m = 0.f, qq = 0.f;
#pragma unroll
            for (int j = 0; j < 64; j++) { float v = osh[j]; m += v; qq += v * v; }
            m *= (1.f / 64.f);
            float var = qq * (1.f / 64.f) - m * m;
            float sln = (osh[d] - m) * rsqrtf(var + EPSF) * gsl[d] + bsl[d];
            float qd = sln * tq[((size_t)k * 64 + d) * 64 + d];
            float invden = 1.f / (sigma_d * sigma_d + EPSF);
            g_a[bk * 64 + d]  = -0.5f * invden;
            g_bq[bk * 64 + d] = qd * invden;
            float cp = -logf(fmaxf(sigma_d, EPSF)) - 0.5f * qd * qd * invden;
#pragma unroll
            for (int o = 1; o < 16; o <<= 1) cp += __shfl_xor_sync(0xffffffffu, cp, o);
            if ((d & 15) == 0)
                g_C[bk * 4 + h] = logf(Nk * (1.f / (float)NN) + EPSF) + LOGPI_SUM + cp;
            g_S2[bk * 64 + d] = 0.f;
            if (d < 4) g_A[bk * 4 + d] = 0.f;
        }
        for (int i = t; i < 256; i += 128) g_T[bk * 256 + i] = 0.f;
    }
}

// ---------------- launch ----------------------------------------------------
extern "C" void kernel_launch(void* const* d_in, const int* in_sizes, int n_in,
                              void* d_out, int out_size) {
    const float* emb   = (const float*)d_in[0];
    const float* mu    = (const float*)d_in[1];
    const float* ls    = (const float*)d_in[2];
    const float* mix0  = (const float*)d_in[3];
    const float* tk    = (const float*)d_in[4];
    const float* tq    = (const float*)d_in[5];
    const float* tv    = (const float*)d_in[6];
    const float* wih   = (const float*)d_in[7];
    const float* whh   = (const float*)d_in[8];
    const float* bih   = (const float*)d_in[9];
    const float* bhh   = (const float*)d_in[10];
    const float* w1    = (const float*)d_in[11];
    const float* b1    = (const float*)d_in[12];
    const float* w2    = (const float*)d_in[13];
    const float* b2    = (const float*)d_in[14];
    const float* ling  = (const float*)d_in[15];
    const float* linb  = (const float*)d_in[16];
    const float* lslg  = (const float*)d_in[17];
    const float* lslb  = (const float*)d_in[18];
    const float* lffg  = (const float*)d_in[19];
    const float* lffb  = (const float*)d_in[20];
    const float* nzi   = (const float*)d_in[21];
    const float* nzf   = (const float*)d_in[22];

    float* out_slots = (float*)d_out;                  // [B,K,D]
    float* out_attn  = (float*)d_out + BB * KK * DD;   // [B,K,N,H]

    k_init_pre<<<BB * KK, 64>>>(mu, ls, mix0, nzi, tq, lslg, lslb);
    k_ln<<<BB * NN / 8, 256>>>(emb, ling, linb);
    k_keys<<<BB * 32, 128>>>(tk);
    for (int it = 0; it < 3; it++) {
        int last = (it == 2);
        k_pass<<<BB * 32, 256>>>(out_attn, last);
        k_upd<<<BB * KK, 128>>>(tk, tv, wih, whh, bih, bhh, w1, b1, w2, b2,
                                lffg, lffb, tq, lslg, lslb, nzf, out_slots, last);
    }
}

// round 14
// speedup vs baseline: 1.0746x; 1.0746x over previous
#include <cuda_runtime.h>
#include <math.h>

#define BB 16
#define NN 4096
#define DD 64
#define KK 8
#define HH 4
#define EPSF 1e-5f
// 16 * (-0.5 * 64 * ln(2*pi))
#define LOGPI_SUM (-940.99305800158484f)

typedef unsigned long long ull;

// ---------------- packed f32x2 helpers --------------------------------------
__device__ __forceinline__ ull pk2(float x, float y) {
    ull r; asm("mov.b64 %0, {%1, %2};" : "=l"(r) : "f"(x), "f"(y)); return r;
}
__device__ __forceinline__ void fma2(ull& d, ull a, ull b) {
    asm("fma.rn.f32x2 %0, %1, %2, %0;" : "+l"(d) : "l"(a), "l"(b));
}
__device__ __forceinline__ ull fma2r(ull a, ull b, ull c) {
    ull d; asm("fma.rn.f32x2 %0, %1, %2, %3;" : "=l"(d) : "l"(a), "l"(b), "l"(c)); return d;
}
__device__ __forceinline__ ull mul2(ull a, ull b) {
    ull d; asm("mul.rn.f32x2 %0, %1, %2;" : "=l"(d) : "l"(a), "l"(b)); return d;
}
union F4U { float4 v; ull u[2]; float s[4]; };

// ---------------- scratch (static device memory) ---------------------------
__device__ float g_x[BB * NN * DD];
__device__ float g_keys[(size_t)BB * NN * KK * DD];    // [b][n][k][d]
__device__ float g_slots[BB * KK * DD];
__device__ float g_sigma[BB * KK * DD];
__device__ float g_a[BB * KK * DD];     // -0.5/(sigma^2+eps)
__device__ float g_bq[BB * KK * DD];    // q/(sigma^2+eps)
__device__ float g_C[BB * KK * HH];     // logit bias per (b,k,h)
__device__ float g_A[BB * KK * HH];     // sum attn
__device__ float g_S2[BB * KK * DD];    // sum attn*k^2
__device__ float g_T[BB * KK * HH * DD];// sum attn*x  [b][k][h][e]

// ---------------- init + first-iteration coefficients ----------------------
__global__ void k_init_pre(const float* __restrict__ mu, const float* __restrict__ ls,
                           const float* __restrict__ mix0, const float* __restrict__ noise,
                           const float* __restrict__ tq, const float* __restrict__ gsl,
                           const float* __restrict__ bsl) {
    int bk = blockIdx.x, k = bk & (KK - 1);
    int d = threadIdx.x, h = d >> 4;
    __shared__ float sh[64];
    float sg = expf(ls[k * 64 + d]);
    float slot = mu[k * 64 + d] + sg * noise[bk * 64 + d];
    g_sigma[bk * 64 + d] = sg;
    g_slots[bk * 64 + d] = slot;
    sh[d] = slot;
    __syncthreads();
    float m = 0.f, q = 0.f;
#pragma unroll
    for (int j = 0; j < 64; j++) { float v = sh[j]; m += v; q += v * v; }
    m *= (1.f / 64.f);
    float var = q * (1.f / 64.f) - m * m;
    float sln = (slot - m) * rsqrtf(var + EPSF) * gsl[d] + bsl[d];
    float qd = sln * tq[((size_t)k * 64 + d) * 64 + d];
    float invden = 1.f / (sg * sg + EPSF);
    g_a[bk * 64 + d] = -0.5f * invden;
    g_bq[bk * 64 + d] = qd * invden;
    float cp = -logf(fmaxf(sg, EPSF)) - 0.5f * qd * qd * invden;
#pragma unroll
    for (int o = 1; o < 16; o <<= 1) cp += __shfl_xor_sync(0xffffffffu, cp, o);
    if ((d & 15) == 0) g_C[bk * 4 + h] = logf(mix0[k] + EPSF) + LOGPI_SUM + cp;
    g_S2[bk * 64 + d] = 0.f;
    if (d < 4) g_A[bk * 4 + d] = 0.f;
#pragma unroll
    for (int i = 0; i < 4; i++) g_T[bk * 256 + i * 64 + d] = 0.f;
}

// ---------------- fused LayerNorm + keys GEMM (k_ln deleted) ----------------
// Fill transposed tile with RAW emb (same access pattern as R6), per-row LN
// in-kernel (conflict-free column reads/writes), write g_x for k_pass, then
// the unchanged 8n x 8d FFMA2 GEMM.
__global__ __launch_bounds__(128, 4) void k_lnkeys(const float* __restrict__ emb,
                                                   const float* __restrict__ lng,
                                                   const float* __restrict__ lnb,
                                                   const float* __restrict__ tk) {
    __shared__ float xs[64 * 128];   // [e][n]  32 KB (transposed)
    __shared__ float ws[64 * 64];    // [e][d]  16 KB
    int b = blockIdx.x >> 5;
    int n0 = (blockIdx.x & 31) << 7;
    int t = threadIdx.x;
    // raw transpose-fill (identical pattern to R6, source = emb)
    {
        const float4* xg = (const float4*)(emb + ((size_t)b * NN + n0) * 64);
#pragma unroll
        for (int r = 0; r < 16; r++) {
            int idx = t + r * 128;
            int n = idx & 127, e4 = idx >> 7;
            float4 v = xg[n * 16 + e4];
            int e0 = e4 << 2;
            xs[(e0 + 0) * 128 + n] = v.x;
            xs[(e0 + 1) * 128 + n] = v.y;
            xs[(e0 + 2) * 128 + n] = v.z;
            xs[(e0 + 3) * 128 + n] = v.w;
        }
    }
    __syncthreads();
    // per-row LayerNorm: thread t owns row n0+t; column accesses xs[e*128+t]
    // hit consecutive banks across lanes -> conflict-free
    {
        float s = 0.f, q = 0.f;
#pragma unroll 8
        for (int e = 0; e < 64; e++) { float v = xs[e * 128 + t]; s += v; q += v * v; }
        float m = s * (1.f / 64.f);
        float var = q * (1.f / 64.f) - m * m;
        float rr = rsqrtf(var + EPSF);
        float* gx = g_x + ((size_t)b * NN + n0 + t) * 64;
#pragma unroll 4
        for (int e = 0; e < 64; e += 4) {
            float4 o;
            o.x = (xs[(e + 0) * 128 + t] - m) * rr * lng[e + 0] + lnb[e + 0];
            o.y = (xs[(e + 1) * 128 + t] - m) * rr * lng[e + 1] + lnb[e + 1];
            o.z = (xs[(e + 2) * 128 + t] - m) * rr * lng[e + 2] + lnb[e + 2];
            o.w = (xs[(e + 3) * 128 + t] - m) * rr * lng[e + 3] + lnb[e + 3];
            xs[(e + 0) * 128 + t] = o.x;
            xs[(e + 1) * 128 + t] = o.y;
            xs[(e + 2) * 128 + t] = o.z;
            xs[(e + 3) * 128 + t] = o.w;
            *(float4*)&gx[e] = o;
        }
    }
    // (first __syncthreads in the k-loop makes LN writes visible to all warps)
    int tx = t & 7, ty = t >> 3;
    int d0 = tx << 3;     // 0..56
    int nr = ty << 3;     // 0..120
    for (int k = 0; k < KK; k++) {
        __syncthreads();
        const float4* wg = (const float4*)(tk + (size_t)k * 4096);
#pragma unroll
        for (int r = 0; r < 8; r++)
            ((float4*)ws)[t + r * 128] = wg[t + r * 128];
        __syncthreads();
        ull acc[8][4];
#pragma unroll
        for (int n = 0; n < 8; n++)
#pragma unroll
            for (int p = 0; p < 4; p++) acc[n][p] = 0ull;
#pragma unroll 8
        for (int e = 0; e < 64; e++) {
            F4U wa; wa.v = *(const float4*)&ws[e * 64 + d0];
            F4U wb; wb.v = *(const float4*)&ws[e * 64 + d0 + 4];
            F4U xa; xa.v = *(const float4*)&xs[e * 128 + nr];
            F4U xb; xb.v = *(const float4*)&xs[e * 128 + nr + 4];
#pragma unroll
            for (int n = 0; n < 8; n++) {
                float xv = (n < 4) ? xa.s[n] : xb.s[n - 4];
                ull x2 = pk2(xv, xv);
                fma2(acc[n][0], x2, wa.u[0]);
                fma2(acc[n][1], x2, wa.u[1]);
                fma2(acc[n][2], x2, wb.u[0]);
                fma2(acc[n][3], x2, wb.u[1]);
            }
        }
        size_t o0 = (((size_t)b * NN + n0 + nr) * KK + k) * 64 + d0;
#pragma unroll
        for (int n = 0; n < 8; n++) {
            F4U oa, ob;
            oa.u[0] = acc[n][0]; oa.u[1] = acc[n][1];
            ob.u[0] = acc[n][2]; ob.u[1] = acc[n][3];
            *(float4*)&g_keys[o0 + (size_t)n * 512]     = oa.v;
            *(float4*)&g_keys[o0 + (size_t)n * 512 + 4] = ob.v;
        }
    }
}

// ---------------- fused attention pass (two-phase, R6-best, untouched) ------
__global__ __launch_bounds__(256, 2) void k_pass(float* __restrict__ attn_out, int last) {
    __shared__ float4 xs[2048];       // [n][e/4]  32 KB
    __shared__ float attn_s[4096];    // [n][kh]   16 KB (reused as reduction scratch)
    int b = blockIdx.x >> 5;
    int n0 = (blockIdx.x & 31) << 7;
    int t = threadIdx.x, w = t >> 5, lane = t & 31;
    int bk = b * KK + (lane >> 2);
    int h = lane & 3;
    F4U a4[4], b4[4];
#pragma unroll
    for (int i = 0; i < 4; i++) {
        a4[i].v = *(const float4*)&g_a[bk * 64 + h * 16 + i * 4];
        b4[i].v = *(const float4*)&g_bq[bk * 64 + h * 16 + i * 4];
    }
    float C = g_C[bk * 4 + h];
    for (int i = t; i < 2048; i += 256)
        xs[i] = ((const float4*)g_x)[((size_t)b * NN + n0) * 16 + i];
    __syncthreads();

    F4U S2a[4];
#pragma unroll
    for (int j = 0; j < 4; j++) { S2a[j].u[0] = 0ull; S2a[j].u[1] = 0ull; }
    float Aacc = 0.f;
    float* aout = attn_out + (size_t)bk * NN * 4 + h;
    const float4* kbase = ((const float4*)g_keys) + ((size_t)b * NN + n0) * 128 + lane * 4;

    F4U q0, q1, q2, q3;
    { const float4* kp = kbase + (size_t)(w * 16) * 128;
      q0.v = kp[0]; q1.v = kp[1]; q2.v = kp[2]; q3.v = kp[3]; }
#pragma unroll 2
    for (int ni = 0; ni < 16; ni++) {
        int nl = w * 16 + ni;
        ull kp8[8] = {q0.u[0], q0.u[1], q1.u[0], q1.u[1], q2.u[0], q2.u[1], q3.u[0], q3.u[1]};
        if (ni < 15) {
            const float4* kp = kbase + (size_t)(nl + 1) * 128;
            q0.v = kp[0]; q1.v = kp[1]; q2.v = kp[2]; q3.v = kp[3];
        }
        ull lgp = 0ull;
#pragma unroll
        for (int j = 0; j < 8; j++) {
            ull tmp = fma2r(kp8[j], a4[j >> 1].u[j & 1], b4[j >> 1].u[j & 1]);
            lgp = fma2r(kp8[j], tmp, lgp);
        }
        F4U lgu; lgu.u[0] = lgp;
        float lg = C + lgu.s[0] + lgu.s[1];
        float mm = lg;
        mm = fmaxf(mm, __shfl_xor_sync(0xffffffffu, mm, 4));
        mm = fmaxf(mm, __shfl_xor_sync(0xffffffffu, mm, 8));
        mm = fmaxf(mm, __shfl_xor_sync(0xffffffffu, mm, 16));
        float ex = __expf(lg - mm);
        float ss = ex;
        ss += __shfl_xor_sync(0xffffffffu, ss, 4);
        ss += __shfl_xor_sync(0xffffffffu, ss, 8);
        ss += __shfl_xor_sync(0xffffffffu, ss, 16);
        float attn = __fdividef(ex, ss) + EPSF;
        attn_s[nl * 32 + lane] = attn;
        if (last) aout[(size_t)(n0 + nl) * 4] = attn;
        Aacc += attn;
        ull attn2 = pk2(attn, attn);
#pragma unroll
        for (int j = 0; j < 8; j++) {
            ull ak = mul2(attn2, kp8[j]);
            S2a[j >> 1].u[j & 1] = fma2r(ak, kp8[j], S2a[j >> 1].u[j & 1]);
        }
    }
    __syncthreads();

    // ---- phase 2: T[kh][e0..e0+7] = sum_n attn[n][kh] * x[n][e] -------------
    {
        int kh = t >> 3, et = t & 7;
        ull Tl[4] = {0ull, 0ull, 0ull, 0ull};
        const float* ap = attn_s + kh;
        const float4* xp = xs + et * 2;
#pragma unroll 4
        for (int n = 0; n < 128; n++) {
            float at = ap[n * 32];
            ull at2 = pk2(at, at);
            F4U xa; xa.v = xp[n * 16];
            F4U xb; xb.v = xp[n * 16 + 1];
            Tl[0] = fma2r(at2, xa.u[0], Tl[0]);
            Tl[1] = fma2r(at2, xa.u[1], Tl[1]);
            Tl[2] = fma2r(at2, xb.u[0], Tl[2]);
            Tl[3] = fma2r(at2, xb.u[1], Tl[3]);
        }
        int k2 = kh >> 2, h2 = kh & 3;
        float* gp = &g_T[(size_t)(b * KK + k2) * 256 + h2 * 64 + et * 8];
        F4U o0, o1;
        o0.u[0] = Tl[0]; o0.u[1] = Tl[1];
        o1.u[0] = Tl[2]; o1.u[1] = Tl[3];
#pragma unroll
        for (int j = 0; j < 4; j++) atomicAdd(gp + j, o0.s[j]);
#pragma unroll
        for (int j = 0; j < 4; j++) atomicAdd(gp + 4 + j, o1.s[j]);
    }

    // ---- S2 + A tree (reuse attn_s as scratch) ------------------------------
    __syncthreads();
    float* redf = attn_s;
#define SIDX(ww, j) ((ww) * 544 + lane * 17 + (j))
    if (w >= 4) {
#pragma unroll
        for (int j = 0; j < 16; j++) redf[SIDX(w - 4, j)] = S2a[j >> 2].s[j & 3];
        redf[SIDX(w - 4, 16)] = Aacc;
    }
    __syncthreads();
    if (w < 4) {
#pragma unroll
        for (int j = 0; j < 16; j++) S2a[j >> 2].s[j & 3] += redf[SIDX(w, j)];
        Aacc += redf[SIDX(w, 16)];
    }
    __syncthreads();
    if (w == 2 || w == 3) {
#pragma unroll
        for (int j = 0; j < 16; j++) redf[SIDX(w - 2, j)] = S2a[j >> 2].s[j & 3];
        redf[SIDX(w - 2, 16)] = Aacc;
    }
    __syncthreads();
    if (w < 2) {
#pragma unroll
        for (int j = 0; j < 16; j++) S2a[j >> 2].s[j & 3] += redf[SIDX(w, j)];
        Aacc += redf[SIDX(w, 16)];
    }
    __syncthreads();
    if (w == 1) {
#pragma unroll
        for (int j = 0; j < 16; j++) redf[SIDX(0, j)] = S2a[j >> 2].s[j & 3];
        redf[SIDX(0, 16)] = Aacc;
    }
    __syncthreads();
    if (w == 0) {
#pragma unroll
        for (int j = 0; j < 16; j++)
            atomicAdd(&g_S2[(size_t)b * 512 + lane * 16 + j],
                      S2a[j >> 2].s[j & 3] + redf[SIDX(0, j)]);
        atomicAdd(&g_A[b * 32 + lane], Aacc + redf[SIDX(0, 16)]);
    }
}

// ---------------- slot update + fused next-iter pre (128 threads, R6) ------
__global__ __launch_bounds__(128) void k_upd(
        const float* __restrict__ tk, const float* __restrict__ tv,
        const float* __restrict__ wih, const float* __restrict__ whh,
        const float* __restrict__ bih, const float* __restrict__ bhh,
        const float* __restrict__ w1, const float* __restrict__ b1,
        const float* __restrict__ w2, const float* __restrict__ b2,
        const float* __restrict__ gff, const float* __restrict__ bff,
        const float* __restrict__ tq, const float* __restrict__ gsl,
        const float* __restrict__ bsl,
        const float* __restrict__ noisef, float* __restrict__ out_slots, int last) {
    int bk = blockIdx.x;
    int k = bk & (KK - 1);
    int t = threadIdx.x;
    int d = t & 63, half = t >> 6;
    int h = d >> 4;
    __shared__ float Wt[24576];      // 96 KB, reused: gates -> w1T -> w2T
    __shared__ float Tsh[4][64], Ash[4];
    __shared__ float pu[2][64], ps1[2][64];
    __shared__ float ush[64], hsh[64];
    __shared__ float gsh[6][64];
    __shared__ float sh[64], presh[64], h1sh[256], pw2[2][64], osh[64];

    for (int idx = t; idx < 384; idx += 128) {
        int s = idx >= 192;
        int row = idx - s * 192;
        const float4* src = (const float4*)((s ? whh : wih) + (size_t)row * 64);
        float* dst = Wt + s * 12288 + row;
#pragma unroll
        for (int r = 0; r < 16; r++) {
            float4 v = src[r];
            dst[(4 * r + 0) * 192] = v.x;
            dst[(4 * r + 1) * 192] = v.y;
            dst[(4 * r + 2) * 192] = v.z;
            dst[(4 * r + 3) * 192] = v.w;
        }
    }
    for (int i = t; i < 256; i += 128) Tsh[i >> 6][i & 63] = g_T[bk * 256 + i];
    if (t < 4) Ash[t] = g_A[bk * 4 + t];
    if (t >= 64) hsh[d] = g_slots[bk * 64 + d];
    __syncthreads();
    float Nk = Ash[0] + Ash[1] + Ash[2] + Ash[3];
    {
        float u = 0.f, s1 = 0.f;
        int e0 = half * 32;
#pragma unroll 8
        for (int e = e0; e < e0 + 32; e++) {
            float tvv = Tsh[h][e];
            u  = fmaf(tvv, tv[((size_t)k * 64 + e) * 64 + d], u);
            s1 = fmaf(tvv, tk[((size_t)k * 64 + e) * 64 + d], s1);
        }
        pu[half][d] = u; ps1[half][d] = s1;
    }
    __syncthreads();
    float sigma_d = 0.f, u = 0.f;
    if (t < 64) {
        u = pu[0][d] + pu[1][d];
        float s1 = ps1[0][d] + ps1[1][d];
        float invNk = 1.f / Nk;
        u *= (invNk + EPSF);
        float sig2 = fmaxf(g_S2[bk * 64 + d] - 2.f * u * s1 + u * u * Ash[h], 0.f);
        sigma_d = sqrtf(sig2 * invNk) + EPSF;
        g_sigma[bk * 64 + d] = sigma_d;
        ush[d] = u;
    }
    __syncthreads();
    {
        const float* bi = half ? bhh : bih;
        const float* vi = half ? hsh : ush;
        const float* Wb = Wt + half * 12288;
        float g0 = bi[d], g1 = bi[64 + d], g2 = bi[128 + d];
#pragma unroll 8
        for (int e = 0; e < 64; e++) {
            float v = vi[e];
            g0 = fmaf(v, Wb[e * 192 + d], g0);
            g1 = fmaf(v, Wb[e * 192 + 64 + d], g1);
            g2 = fmaf(v, Wb[e * 192 + 128 + d], g2);
        }
        gsh[half * 3 + 0][d] = g0;
        gsh[half * 3 + 1][d] = g1;
        gsh[half * 3 + 2][d] = g2;
    }
    __syncthreads();
    float snew = 0.f;
    if (t < 64) {
        float r = 1.f / (1.f + expf(-(gsh[0][d] + gsh[3][d])));
        float z = 1.f / (1.f + expf(-(gsh[1][d] + gsh[4][d])));
        float nn2 = tanhf(gsh[2][d] + r * gsh[5][d]);
        snew = (1.f - z) * nn2 + z * hsh[d];
        sh[d] = snew;
    }
    for (int idx = t; idx < 256; idx += 128) {
        const float4* src = (const float4*)(w1 + (size_t)idx * 64);
        float* dst = Wt + idx;
#pragma unroll
        for (int r = 0; r < 16; r++) {
            float4 v = src[r];
            dst[(4 * r + 0) * 256] = v.x;
            dst[(4 * r + 1) * 256] = v.y;
            dst[(4 * r + 2) * 256] = v.z;
            dst[(4 * r + 3) * 256] = v.w;
        }
    }
    __syncthreads();
    if (t < 64) {
        float m = 0.f, qq = 0.f;
#pragma unroll
        for (int j = 0; j < 64; j++) { float v = sh[j]; m += v; qq += v * v; }
        m *= (1.f / 64.f);
        float var = qq * (1.f / 64.f) - m * m;
        presh[d] = (snew - m) * rsqrtf(var + EPSF) * gff[d] + bff[d];
    }
    __syncthreads();
    for (int j = t; j < 256; j += 128) {
        float acc = b1[j];
#pragma unroll 8
        for (int e = 0; e < 64; e++) acc = fmaf(presh[e], Wt[e * 256 + j], acc);
        h1sh[j] = fmaxf(acc, 0.f);
    }
    __syncthreads();
    for (int uu = t; uu < 256; uu += 128) {
        int row = uu & 63, q = uu >> 6;
        const float4* src = (const float4*)(w2 + (size_t)row * 256 + q * 64);
        float* dst = Wt + row;
#pragma unroll
        for (int r = 0; r < 16; r++) {
            float4 v = src[r];
            dst[(q * 64 + 4 * r + 0) * 64] = v.x;
            dst[(q * 64 + 4 * r + 1) * 64] = v.y;
            dst[(q * 64 + 4 * r + 2) * 64] = v.z;
            dst[(q * 64 + 4 * r + 3) * 64] = v.w;
        }
    }
    __syncthreads();
    {
        float o = 0.f;
        int j0 = half * 128;
#pragma unroll 8
        for (int j = j0; j < j0 + 128; j++) o = fmaf(h1sh[j], Wt[j * 64 + d], o);
        pw2[half][d] = o;
    }
    __syncthreads();
    if (t < 64) {
        float o = sh[d] + b2[d] + pw2[0][d] + pw2[1][d];
        g_slots[bk * 64 + d] = o;
        if (last) out_slots[bk * 64 + d] = o + sigma_d * noisef[bk * 64 + d];
        osh[d] = o;
    }
    __syncthreads();
    if (!last) {
        if (t < 64) {
            float m = 0.f, qq = 0.f;
#pragma unroll
            for (int j = 0; j < 64; j++) { float v = osh[j]; m += v; qq += v * v; }
            m *= (1.f / 64.f);
            float var = qq * (1.f / 64.f) - m * m;
            float sln = (osh[d] - m) * rsqrtf(var + EPSF) * gsl[d] + bsl[d];
            float qd = sln * tq[((size_t)k * 64 + d) * 64 + d];
            float invden = 1.f / (sigma_d * sigma_d + EPSF);
            g_a[bk * 64 + d]  = -0.5f * invden;
            g_bq[bk * 64 + d] = qd * invden;
            float cp = -logf(fmaxf(sigma_d, EPSF)) - 0.5f * qd * qd * invden;
#pragma unroll
            for (int o = 1; o < 16; o <<= 1) cp += __shfl_xor_sync(0xffffffffu, cp, o);
            if ((d & 15) == 0)
                g_C[bk * 4 + h] = logf(Nk * (1.f / (float)NN) + EPSF) + LOGPI_SUM + cp;
            g_S2[bk * 64 + d] = 0.f;
            if (d < 4) g_A[bk * 4 + d] = 0.f;
        }
        for (int i = t; i < 256; i += 128) g_T[bk * 256 + i] = 0.f;
    }
}

// ---------------- launch ----------------------------------------------------
extern "C" void kernel_launch(void* const* d_in, const int* in_sizes, int n_in,
                              void* d_out, int out_size) {
    const float* emb   = (const float*)d_in[0];
    const float* mu    = (const float*)d_in[1];
    const float* ls    = (const float*)d_in[2];
    const float* mix0  = (const float*)d_in[3];
    const float* tk    = (const float*)d_in[4];
    const float* tq    = (const float*)d_in[5];
    const float* tv    = (const float*)d_in[6];
    const float* wih   = (const float*)d_in[7];
    const float* whh   = (const float*)d_in[8];
    const float* bih   = (const float*)d_in[9];
    const float* bhh   = (const float*)d_in[10];
    const float* w1    = (const float*)d_in[11];
    const float* b1    = (const float*)d_in[12];
    const float* w2    = (const float*)d_in[13];
    const float* b2    = (const float*)d_in[14];
    const float* ling  = (const float*)d_in[15];
    const float* linb  = (const float*)d_in[16];
    const float* lslg  = (const float*)d_in[17];
    const float* lslb  = (const float*)d_in[18];
    const float* lffg  = (const float*)d_in[19];
    const float* lffb  = (const float*)d_in[20];
    const float* nzi   = (const float*)d_in[21];
    const float* nzf   = (const float*)d_in[22];

    float* out_slots = (float*)d_out;                  // [B,K,D]
    float* out_attn  = (float*)d_out + BB * KK * DD;   // [B,K,N,H]

    k_init_pre<<<BB * KK, 64>>>(mu, ls, mix0, nzi, tq, lslg, lslb);
    k_lnkeys<<<BB * 32, 128>>>(emb, ling, linb, tk);
    for (int it = 0; it < 3; it++) {
        int last = (it == 2);
        k_pass<<<BB * 32, 256>>>(out_attn, last);
        k_upd<<<BB * KK, 128>>>(tk, tv, wih, whh, bih, bhh, w1, b1, w2, b2,
                                lffg, lffb, tq, lslg, lslb, nzf, out_slots, last);
    }
}

// round 15
// speedup vs baseline: 1.1191x; 1.0414x over previous
#include <cuda_runtime.h>
#include <math.h>

#define BB 16
#define NN 4096
#define DD 64
#define KK 8
#define HH 4
#define EPSF 1e-5f
// 16 * (-0.5 * 64 * ln(2*pi))
#define LOGPI_SUM (-940.99305800158484f)

typedef unsigned long long ull;

// ---------------- packed f32x2 helpers --------------------------------------
__device__ __forceinline__ ull pk2(float x, float y) {
    ull r; asm("mov.b64 %0, {%1, %2};" : "=l"(r) : "f"(x), "f"(y)); return r;
}
__device__ __forceinline__ void fma2(ull& d, ull a, ull b) {
    asm("fma.rn.f32x2 %0, %1, %2, %0;" : "+l"(d) : "l"(a), "l"(b));
}
__device__ __forceinline__ ull fma2r(ull a, ull b, ull c) {
    ull d; asm("fma.rn.f32x2 %0, %1, %2, %3;" : "=l"(d) : "l"(a), "l"(b), "l"(c)); return d;
}
__device__ __forceinline__ ull mul2(ull a, ull b) {
    ull d; asm("mul.rn.f32x2 %0, %1, %2;" : "=l"(d) : "l"(a), "l"(b)); return d;
}
union F4U { float4 v; ull u[2]; float s[4]; };

// ---------------- scratch (static device memory) ---------------------------
__device__ float g_x[BB * NN * DD];
__device__ float g_keys[(size_t)BB * NN * KK * DD];    // [b][n][k][d]
__device__ float g_slots[BB * KK * DD];
__device__ float g_sigma[BB * KK * DD];
__device__ float g_a[BB * KK * DD];     // -0.5/(sigma^2+eps)
__device__ float g_bq[BB * KK * DD];    // q/(sigma^2+eps)
__device__ float g_C[BB * KK * HH];     // logit bias per (b,k,h)
__device__ float g_A[BB * KK * HH];     // sum attn
__device__ float g_S2[BB * KK * DD];    // sum attn*k^2
__device__ float g_T[BB * KK * HH * DD];// sum attn*x  [b][k][h][e]

// ---------------- init + first-iteration coefficients ----------------------
__global__ void k_init_pre(const float* __restrict__ mu, const float* __restrict__ ls,
                           const float* __restrict__ mix0, const float* __restrict__ noise,
                           const float* __restrict__ tq, const float* __restrict__ gsl,
                           const float* __restrict__ bsl) {
    int bk = blockIdx.x, k = bk & (KK - 1);
    int d = threadIdx.x, h = d >> 4;
    __shared__ float sh[64];
    float sg = expf(ls[k * 64 + d]);
    float slot = mu[k * 64 + d] + sg * noise[bk * 64 + d];
    g_sigma[bk * 64 + d] = sg;
    g_slots[bk * 64 + d] = slot;
    sh[d] = slot;
    __syncthreads();
    float m = 0.f, q = 0.f;
#pragma unroll
    for (int j = 0; j < 64; j++) { float v = sh[j]; m += v; q += v * v; }
    m *= (1.f / 64.f);
    float var = q * (1.f / 64.f) - m * m;
    float sln = (slot - m) * rsqrtf(var + EPSF) * gsl[d] + bsl[d];
    float qd = sln * tq[((size_t)k * 64 + d) * 64 + d];
    float invden = 1.f / (sg * sg + EPSF);
    g_a[bk * 64 + d] = -0.5f * invden;
    g_bq[bk * 64 + d] = qd * invden;
    float cp = -logf(fmaxf(sg, EPSF)) - 0.5f * qd * qd * invden;
#pragma unroll
    for (int o = 1; o < 16; o <<= 1) cp += __shfl_xor_sync(0xffffffffu, cp, o);
    if ((d & 15) == 0) g_C[bk * 4 + h] = logf(mix0[k] + EPSF) + LOGPI_SUM + cp;
    g_S2[bk * 64 + d] = 0.f;
    if (d < 4) g_A[bk * 4 + d] = 0.f;
#pragma unroll
    for (int i = 0; i < 4; i++) g_T[bk * 256 + i * 64 + d] = 0.f;
}

// ---------------- fused LayerNorm + keys GEMM -------------------------------
__global__ __launch_bounds__(128, 4) void k_lnkeys(const float* __restrict__ emb,
                                                   const float* __restrict__ lng,
                                                   const float* __restrict__ lnb,
                                                   const float* __restrict__ tk) {
    __shared__ float xs[64 * 128];   // [e][n]  32 KB (transposed)
    __shared__ float ws[64 * 64];    // [e][d]  16 KB
    int b = blockIdx.x >> 5;
    int n0 = (blockIdx.x & 31) << 7;
    int t = threadIdx.x;
    {
        const float4* xg = (const float4*)(emb + ((size_t)b * NN + n0) * 64);
#pragma unroll
        for (int r = 0; r < 16; r++) {
            int idx = t + r * 128;
            int n = idx & 127, e4 = idx >> 7;
            float4 v = xg[n * 16 + e4];
            int e0 = e4 << 2;
            xs[(e0 + 0) * 128 + n] = v.x;
            xs[(e0 + 1) * 128 + n] = v.y;
            xs[(e0 + 2) * 128 + n] = v.z;
            xs[(e0 + 3) * 128 + n] = v.w;
        }
    }
    __syncthreads();
    {
        float s = 0.f, q = 0.f;
#pragma unroll 8
        for (int e = 0; e < 64; e++) { float v = xs[e * 128 + t]; s += v; q += v * v; }
        float m = s * (1.f / 64.f);
        float var = q * (1.f / 64.f) - m * m;
        float rr = rsqrtf(var + EPSF);
        float* gx = g_x + ((size_t)b * NN + n0 + t) * 64;
#pragma unroll 4
        for (int e = 0; e < 64; e += 4) {
            float4 o;
            o.x = (xs[(e + 0) * 128 + t] - m) * rr * lng[e + 0] + lnb[e + 0];
            o.y = (xs[(e + 1) * 128 + t] - m) * rr * lng[e + 1] + lnb[e + 1];
            o.z = (xs[(e + 2) * 128 + t] - m) * rr * lng[e + 2] + lnb[e + 2];
            o.w = (xs[(e + 3) * 128 + t] - m) * rr * lng[e + 3] + lnb[e + 3];
            xs[(e + 0) * 128 + t] = o.x;
            xs[(e + 1) * 128 + t] = o.y;
            xs[(e + 2) * 128 + t] = o.z;
            xs[(e + 3) * 128 + t] = o.w;
            *(float4*)&gx[e] = o;
        }
    }
    int tx = t & 7, ty = t >> 3;
    int d0 = tx << 3;     // 0..56
    int nr = ty << 3;     // 0..120
    for (int k = 0; k < KK; k++) {
        __syncthreads();
        const float4* wg = (const float4*)(tk + (size_t)k * 4096);
#pragma unroll
        for (int r = 0; r < 8; r++)
            ((float4*)ws)[t + r * 128] = wg[t + r * 128];
        __syncthreads();
        ull acc[8][4];
#pragma unroll
        for (int n = 0; n < 8; n++)
#pragma unroll
            for (int p = 0; p < 4; p++) acc[n][p] = 0ull;
#pragma unroll 8
        for (int e = 0; e < 64; e++) {
            F4U wa; wa.v = *(const float4*)&ws[e * 64 + d0];
            F4U wb; wb.v = *(const float4*)&ws[e * 64 + d0 + 4];
            F4U xa; xa.v = *(const float4*)&xs[e * 128 + nr];
            F4U xb; xb.v = *(const float4*)&xs[e * 128 + nr + 4];
#pragma unroll
            for (int n = 0; n < 8; n++) {
                float xv = (n < 4) ? xa.s[n] : xb.s[n - 4];
                ull x2 = pk2(xv, xv);
                fma2(acc[n][0], x2, wa.u[0]);
                fma2(acc[n][1], x2, wa.u[1]);
                fma2(acc[n][2], x2, wb.u[0]);
                fma2(acc[n][3], x2, wb.u[1]);
            }
        }
        size_t o0 = (((size_t)b * NN + n0 + nr) * KK + k) * 64 + d0;
#pragma unroll
        for (int n = 0; n < 8; n++) {
            F4U oa, ob;
            oa.u[0] = acc[n][0]; oa.u[1] = acc[n][1];
            ob.u[0] = acc[n][2]; ob.u[1] = acc[n][3];
            *(float4*)&g_keys[o0 + (size_t)n * 512]     = oa.v;
            *(float4*)&g_keys[o0 + (size_t)n * 512 + 4] = ob.v;
        }
    }
}

// ---------------- fused attention pass (two-phase, R6-best, untouched) ------
__global__ __launch_bounds__(256, 2) void k_pass(float* __restrict__ attn_out, int last) {
    __shared__ float4 xs[2048];       // [n][e/4]  32 KB
    __shared__ float attn_s[4096];    // [n][kh]   16 KB
    int b = blockIdx.x >> 5;
    int n0 = (blockIdx.x & 31) << 7;
    int t = threadIdx.x, w = t >> 5, lane = t & 31;
    int bk = b * KK + (lane >> 2);
    int h = lane & 3;
    F4U a4[4], b4[4];
#pragma unroll
    for (int i = 0; i < 4; i++) {
        a4[i].v = *(const float4*)&g_a[bk * 64 + h * 16 + i * 4];
        b4[i].v = *(const float4*)&g_bq[bk * 64 + h * 16 + i * 4];
    }
    float C = g_C[bk * 4 + h];
    for (int i = t; i < 2048; i += 256)
        xs[i] = ((const float4*)g_x)[((size_t)b * NN + n0) * 16 + i];
    __syncthreads();

    F4U S2a[4];
#pragma unroll
    for (int j = 0; j < 4; j++) { S2a[j].u[0] = 0ull; S2a[j].u[1] = 0ull; }
    float Aacc = 0.f;
    float* aout = attn_out + (size_t)bk * NN * 4 + h;
    const float4* kbase = ((const float4*)g_keys) + ((size_t)b * NN + n0) * 128 + lane * 4;

    F4U q0, q1, q2, q3;
    { const float4* kp = kbase + (size_t)(w * 16) * 128;
      q0.v = kp[0]; q1.v = kp[1]; q2.v = kp[2]; q3.v = kp[3]; }
#pragma unroll 2
    for (int ni = 0; ni < 16; ni++) {
        int nl = w * 16 + ni;
        ull kp8[8] = {q0.u[0], q0.u[1], q1.u[0], q1.u[1], q2.u[0], q2.u[1], q3.u[0], q3.u[1]};
        if (ni < 15) {
            const float4* kp = kbase + (size_t)(nl + 1) * 128;
            q0.v = kp[0]; q1.v = kp[1]; q2.v = kp[2]; q3.v = kp[3];
        }
        ull lgp = 0ull;
#pragma unroll
        for (int j = 0; j < 8; j++) {
            ull tmp = fma2r(kp8[j], a4[j >> 1].u[j & 1], b4[j >> 1].u[j & 1]);
            lgp = fma2r(kp8[j], tmp, lgp);
        }
        F4U lgu; lgu.u[0] = lgp;
        float lg = C + lgu.s[0] + lgu.s[1];
        float mm = lg;
        mm = fmaxf(mm, __shfl_xor_sync(0xffffffffu, mm, 4));
        mm = fmaxf(mm, __shfl_xor_sync(0xffffffffu, mm, 8));
        mm = fmaxf(mm, __shfl_xor_sync(0xffffffffu, mm, 16));
        float ex = __expf(lg - mm);
        float ss = ex;
        ss += __shfl_xor_sync(0xffffffffu, ss, 4);
        ss += __shfl_xor_sync(0xffffffffu, ss, 8);
        ss += __shfl_xor_sync(0xffffffffu, ss, 16);
        float attn = __fdividef(ex, ss) + EPSF;
        attn_s[nl * 32 + lane] = attn;
        if (last) aout[(size_t)(n0 + nl) * 4] = attn;
        Aacc += attn;
        ull attn2 = pk2(attn, attn);
#pragma unroll
        for (int j = 0; j < 8; j++) {
            ull ak = mul2(attn2, kp8[j]);
            S2a[j >> 1].u[j & 1] = fma2r(ak, kp8[j], S2a[j >> 1].u[j & 1]);
        }
    }
    __syncthreads();

    {
        int kh = t >> 3, et = t & 7;
        ull Tl[4] = {0ull, 0ull, 0ull, 0ull};
        const float* ap = attn_s + kh;
        const float4* xp = xs + et * 2;
#pragma unroll 4
        for (int n = 0; n < 128; n++) {
            float at = ap[n * 32];
            ull at2 = pk2(at, at);
            F4U xa; xa.v = xp[n * 16];
            F4U xb; xb.v = xp[n * 16 + 1];
            Tl[0] = fma2r(at2, xa.u[0], Tl[0]);
            Tl[1] = fma2r(at2, xa.u[1], Tl[1]);
            Tl[2] = fma2r(at2, xb.u[0], Tl[2]);
            Tl[3] = fma2r(at2, xb.u[1], Tl[3]);
        }
        int k2 = kh >> 2, h2 = kh & 3;
        float* gp = &g_T[(size_t)(b * KK + k2) * 256 + h2 * 64 + et * 8];
        F4U o0, o1;
        o0.u[0] = Tl[0]; o0.u[1] = Tl[1];
        o1.u[0] = Tl[2]; o1.u[1] = Tl[3];
#pragma unroll
        for (int j = 0; j < 4; j++) atomicAdd(gp + j, o0.s[j]);
#pragma unroll
        for (int j = 0; j < 4; j++) atomicAdd(gp + 4 + j, o1.s[j]);
    }

    __syncthreads();
    float* redf = attn_s;
#define SIDX(ww, j) ((ww) * 544 + lane * 17 + (j))
    if (w >= 4) {
#pragma unroll
        for (int j = 0; j < 16; j++) redf[SIDX(w - 4, j)] = S2a[j >> 2].s[j & 3];
        redf[SIDX(w - 4, 16)] = Aacc;
    }
    __syncthreads();
    if (w < 4) {
#pragma unroll
        for (int j = 0; j < 16; j++) S2a[j >> 2].s[j & 3] += redf[SIDX(w, j)];
        Aacc += redf[SIDX(w, 16)];
    }
    __syncthreads();
    if (w == 2 || w == 3) {
#pragma unroll
        for (int j = 0; j < 16; j++) redf[SIDX(w - 2, j)] = S2a[j >> 2].s[j & 3];
        redf[SIDX(w - 2, 16)] = Aacc;
    }
    __syncthreads();
    if (w < 2) {
#pragma unroll
        for (int j = 0; j < 16; j++) S2a[j >> 2].s[j & 3] += redf[SIDX(w, j)];
        Aacc += redf[SIDX(w, 16)];
    }
    __syncthreads();
    if (w == 1) {
#pragma unroll
        for (int j = 0; j < 16; j++) redf[SIDX(0, j)] = S2a[j >> 2].s[j & 3];
        redf[SIDX(0, 16)] = Aacc;
    }
    __syncthreads();
    if (w == 0) {
#pragma unroll
        for (int j = 0; j < 16; j++)
            atomicAdd(&g_S2[(size_t)b * 512 + lane * 16 + j],
                      S2a[j >> 2].s[j & 3] + redf[SIDX(0, j)]);
        atomicAdd(&g_A[b * 32 + lane], Aacc + redf[SIDX(0, 16)]);
    }
}

// ---------------- slot update: 256 threads, hoisted staging -----------------
__global__ __launch_bounds__(256) void k_upd(
        const float* __restrict__ tk, const float* __restrict__ tv,
        const float* __restrict__ wih, const float* __restrict__ whh,
        const float* __restrict__ bih, const float* __restrict__ bhh,
        const float* __restrict__ w1, const float* __restrict__ b1,
        const float* __restrict__ w2, const float* __restrict__ b2,
        const float* __restrict__ gff, const float* __restrict__ bff,
        const float* __restrict__ tq, const float* __restrict__ gsl,
        const float* __restrict__ bsl,
        const float* __restrict__ noisef, float* __restrict__ out_slots, int last) {
    int bk = blockIdx.x;
    int k = bk & (KK - 1);
    int t = threadIdx.x;
    int d = t & 63, quar = t >> 6;     // quarter 0..3
    int h = d >> 4;
    __shared__ float Wt[24576];        // gates [s][e*192+row]; later reused for w2 [j*64+d]
    __shared__ float W1s[16384];       // w1 [e*256+j]
    __shared__ float Tsh[4][64], Ash[4];
    __shared__ float pu[4][64], ps1[4][64];
    __shared__ float ush[64], hsh[64];
    __shared__ float gsh[6][64];
    __shared__ float sh[64], presh[64], h1sh[256], pw2[4][64], osh[64];

    // ---- hoisted staging: gates + w1 issued before first sync ----
    for (int idx = t; idx < 384; idx += 256) {
        int s = idx >= 192;
        int row = idx - s * 192;
        const float4* src = (const float4*)((s ? whh : wih) + (size_t)row * 64);
        float* dst = Wt + s * 12288 + row;
#pragma unroll
        for (int r = 0; r < 16; r++) {
            float4 v = src[r];
            dst[(4 * r + 0) * 192] = v.x;
            dst[(4 * r + 1) * 192] = v.y;
            dst[(4 * r + 2) * 192] = v.z;
            dst[(4 * r + 3) * 192] = v.w;
        }
    }
    {   // w1 row t (one per thread)
        const float4* src = (const float4*)(w1 + (size_t)t * 64);
        float* dst = W1s + t;
#pragma unroll
        for (int r = 0; r < 16; r++) {
            float4 v = src[r];
            dst[(4 * r + 0) * 256] = v.x;
            dst[(4 * r + 1) * 256] = v.y;
            dst[(4 * r + 2) * 256] = v.z;
            dst[(4 * r + 3) * 256] = v.w;
        }
    }
    if (t < 256) Tsh[t >> 6][t & 63] = g_T[bk * 256 + t];
    if (t < 4) Ash[t] = g_A[bk * 4 + t];
    if (t >= 64 && t < 128) hsh[d] = g_slots[bk * 64 + d];
    __syncthreads();
    float Nk = Ash[0] + Ash[1] + Ash[2] + Ash[3];
    // ---- u/s1 dots: e split over 4 quarters ----
    {
        float u = 0.f, s1 = 0.f;
        int e0 = quar * 16;
#pragma unroll
        for (int e = e0; e < e0 + 16; e++) {
            float tvv = Tsh[h][e];
            u  = fmaf(tvv, tv[((size_t)k * 64 + e) * 64 + d], u);
            s1 = fmaf(tvv, tk[((size_t)k * 64 + e) * 64 + d], s1);
        }
        pu[quar][d] = u; ps1[quar][d] = s1;
    }
    __syncthreads();
    float sigma_d = 0.f;
    if (t < 64) {
        float u = pu[0][d] + pu[1][d] + pu[2][d] + pu[3][d];
        float s1 = ps1[0][d] + ps1[1][d] + ps1[2][d] + ps1[3][d];
        float invNk = 1.f / Nk;
        u *= (invNk + EPSF);
        float sig2 = fmaxf(g_S2[bk * 64 + d] - 2.f * u * s1 + u * u * Ash[h], 0.f);
        sigma_d = sqrtf(sig2 * invNk) + EPSF;
        g_sigma[bk * 64 + d] = sigma_d;
        ush[d] = u;
    }
    __syncthreads();
    // ---- gates: 384 dots over 256 threads (t<128 does two) ----
    {
        int g1i = t;                    // dot 0..255
        int gA = g1i >> 6, dA = g1i & 63;
        const float* viA = (gA < 3) ? ush : hsh;
        const float* WA = Wt + (gA < 3 ? 0 : 12288) + (gA % 3) * 64 + dA;
        float accA = (gA < 3 ? bih : bhh)[(gA % 3) * 64 + dA];
        if (t < 128) {
            int g2i = t + 256;          // dot 256..383
            int gB = g2i >> 6, dB = g2i & 63;
            const float* viB = (gB < 3) ? ush : hsh;
            const float* WB = Wt + (gB < 3 ? 0 : 12288) + (gB % 3) * 64 + dB;
            float accB = (gB < 3 ? bih : bhh)[(gB % 3) * 64 + dB];
#pragma unroll 8
            for (int e = 0; e < 64; e++) {
                accA = fmaf(viA[e], WA[e * 192], accA);
                accB = fmaf(viB[e], WB[e * 192], accB);
            }
            gsh[gB][dB] = accB;
        } else {
#pragma unroll 8
            for (int e = 0; e < 64; e++)
                accA = fmaf(viA[e], WA[e * 192], accA);
        }
        gsh[gA][dA] = accA;
    }
    __syncthreads();
    // ---- snew (t<64) + stage w2 into Wt (gates reads done) ----
    float snew = 0.f;
    if (t < 64) {
        float r = 1.f / (1.f + expf(-(gsh[0][d] + gsh[3][d])));
        float z = 1.f / (1.f + expf(-(gsh[1][d] + gsh[4][d])));
        float nn2 = tanhf(gsh[2][d] + r * gsh[5][d]);
        snew = (1.f - z) * nn2 + z * hsh[d];
        sh[d] = snew;
    }
    {   // w2: row = t&63 (d), quarter q2 = t>>6 of the j range
        int row = t & 63, q2 = t >> 6;
        const float4* src = (const float4*)(w2 + (size_t)row * 256 + q2 * 64);
        float* dst = Wt + row;
#pragma unroll
        for (int r = 0; r < 16; r++) {
            float4 v = src[r];
            dst[(q2 * 64 + 4 * r + 0) * 64] = v.x;
            dst[(q2 * 64 + 4 * r + 1) * 64] = v.y;
            dst[(q2 * 64 + 4 * r + 2) * 64] = v.z;
            dst[(q2 * 64 + 4 * r + 3) * 64] = v.w;
        }
    }
    __syncthreads();
    if (t < 64) {
        float m = 0.f, qq = 0.f;
#pragma unroll
        for (int j = 0; j < 64; j++) { float v = sh[j]; m += v; qq += v * v; }
        m *= (1.f / 64.f);
        float var = qq * (1.f / 64.f) - m * m;
        presh[d] = (snew - m) * rsqrtf(var + EPSF) * gff[d] + bff[d];
    }
    __syncthreads();
    {   // h1: one dot per thread
        float acc = b1[t];
        const float* wr = W1s + t;
#pragma unroll 8
        for (int e = 0; e < 64; e++) acc = fmaf(presh[e], wr[e * 256], acc);
        h1sh[t] = fmaxf(acc, 0.f);
    }
    __syncthreads();
    {   // w2 dot: j split over 4 quarters
        float o = 0.f;
        int j0 = quar * 64;
#pragma unroll 8
        for (int j = j0; j < j0 + 64; j++) o = fmaf(h1sh[j], Wt[j * 64 + d], o);
        pw2[quar][d] = o;
    }
    __syncthreads();
    if (t < 64) {
        float o = sh[d] + b2[d] + pw2[0][d] + pw2[1][d] + pw2[2][d] + pw2[3][d];
        g_slots[bk * 64 + d] = o;
        if (last) out_slots[bk * 64 + d] = o + sigma_d * noisef[bk * 64 + d];
        osh[d] = o;
    }
    __syncthreads();
    if (!last) {
        if (t < 64) {
            float m = 0.f, qq = 0.f;
#pragma unroll
            for (int j = 0; j < 64; j++) { float v = osh[j]; m += v; qq += v * v; }
            m *= (1.f / 64.f);
            float var = qq * (1.f / 64.f) - m * m;
            float sln = (osh[d] - m) * rsqrtf(var + EPSF) * gsl[d] + bsl[d];
            float qd = sln * tq[((size_t)k * 64 + d) * 64 + d];
            float invden = 1.f / (sigma_d * sigma_d + EPSF);
            g_a[bk * 64 + d]  = -0.5f * invden;
            g_bq[bk * 64 + d] = qd * invden;
            float cp = -logf(fmaxf(sigma_d, EPSF)) - 0.5f * qd * qd * invden;
#pragma unroll
            for (int o = 1; o < 16; o <<= 1) cp += __shfl_xor_sync(0xffffffffu, cp, o);
            if ((d & 15) == 0)
                g_C[bk * 4 + h] = logf(Nk * (1.f / (float)NN) + EPSF) + LOGPI_SUM + cp;
            g_S2[bk * 64 + d] = 0.f;
            if (d < 4) g_A[bk * 4 + d] = 0.f;
        }
        if (t < 256) g_T[bk * 256 + t] = 0.f;
    }
}

// ---------------- launch ----------------------------------------------------
extern "C" void kernel_launch(void* const* d_in, const int* in_sizes, int n_in,
                              void* d_out, int out_size) {
    const float* emb   = (const float*)d_in[0];
    const float* mu    = (const float*)d_in[1];
    const float* ls    = (const float*)d_in[2];
    const float* mix0  = (const float*)d_in[3];
    const float* tk    = (const float*)d_in[4];
    const float* tq    = (const float*)d_in[5];
    const float* tv    = (const float*)d_in[6];
    const float* wih   = (const float*)d_in[7];
    const float* whh   = (const float*)d_in[8];
    const float* bih   = (const float*)d_in[9];
    const float* bhh   = (const float*)d_in[10];
    const float* w1    = (const float*)d_in[11];
    const float* b1    = (const float*)d_in[12];
    const float* w2    = (const float*)d_in[13];
    const float* b2    = (const float*)d_in[14];
    const float* ling  = (const float*)d_in[15];
    const float* linb  = (const float*)d_in[16];
    const float* lslg  = (const float*)d_in[17];
    const float* lslb  = (const float*)d_in[18];
    const float* lffg  = (const float*)d_in[19];
    const float* lffb  = (const float*)d_in[20];
    const float* nzi   = (const float*)d_in[21];
    const float* nzf   = (const float*)d_in[22];

    float* out_slots = (float*)d_out;                  // [B,K,D]
    float* out_attn  = (float*)d_out + BB * KK * DD;   // [B,K,N,H]

    k_init_pre<<<BB * KK, 64>>>(mu, ls, mix0, nzi, tq, lslg, lslb);
    k_lnkeys<<<BB * 32, 128>>>(emb, ling, linb, tk);
    for (int it = 0; it < 3; it++) {
        int last = (it == 2);
        k_pass<<<BB * 32, 256>>>(out_attn, last);
        k_upd<<<BB * KK, 256>>>(tk, tv, wih, whh, bih, bhh, w1, b1, w2, b2,
                                lffg, lffb, tq, lslg, lslb, nzf, out_slots, last);
    }
}

// round 16
// speedup vs baseline: 1.1496x; 1.0272x over previous
#include <cuda_runtime.h>
#include <math.h>

#define BB 16
#define NN 4096
#define DD 64
#define KK 8
#define HH 4
#define EPSF 1e-5f
// 16 * (-0.5 * 64 * ln(2*pi))
#define LOGPI_SUM (-940.99305800158484f)

typedef unsigned long long ull;

// ---------------- packed f32x2 helpers --------------------------------------
__device__ __forceinline__ ull pk2(float x, float y) {
    ull r; asm("mov.b64 %0, {%1, %2};" : "=l"(r) : "f"(x), "f"(y)); return r;
}
__device__ __forceinline__ void fma2(ull& d, ull a, ull b) {
    asm("fma.rn.f32x2 %0, %1, %2, %0;" : "+l"(d) : "l"(a), "l"(b));
}
__device__ __forceinline__ ull fma2r(ull a, ull b, ull c) {
    ull d; asm("fma.rn.f32x2 %0, %1, %2, %3;" : "=l"(d) : "l"(a), "l"(b), "l"(c)); return d;
}
__device__ __forceinline__ ull mul2(ull a, ull b) {
    ull d; asm("mul.rn.f32x2 %0, %1, %2;" : "=l"(d) : "l"(a), "l"(b)); return d;
}
union F4U { float4 v; ull u[2]; float s[4]; };

// ---------------- scratch (static device memory) ---------------------------
__device__ float g_x[BB * NN * DD];
__device__ float g_keys[(size_t)BB * NN * KK * DD];    // [b][n][k][d]
__device__ float g_slots[BB * KK * DD];
__device__ float g_sigma[BB * KK * DD];
__device__ float g_a[BB * KK * DD];     // -0.5/(sigma^2+eps)
__device__ float g_bq[BB * KK * DD];    // q/(sigma^2+eps)
__device__ float g_C[BB * KK * HH];     // logit bias per (b,k,h)
__device__ float g_A[BB * KK * HH];     // sum attn
__device__ float g_S2[BB * KK * DD];    // sum attn*k^2
__device__ float g_T[BB * KK * HH * DD];// sum attn*x  [b][k][h][e]

// ---------------- fused LayerNorm + keys GEMM + slot init -------------------
// blocks [0,512): LN + keys GEMM.  blocks [512,640): slot/coefficient init.
__global__ __launch_bounds__(128, 4) void k_lnkeys(
        const float* __restrict__ emb, const float* __restrict__ lng,
        const float* __restrict__ lnb, const float* __restrict__ tk,
        const float* __restrict__ mu, const float* __restrict__ ls,
        const float* __restrict__ mix0, const float* __restrict__ noise,
        const float* __restrict__ tq, const float* __restrict__ gsl,
        const float* __restrict__ bsl) {
    __shared__ float xs[64 * 128];   // [e][n]  32 KB (transposed)
    __shared__ float ws[64 * 64];    // [e][d]  16 KB
    int t = threadIdx.x;

    if (blockIdx.x >= BB * 32) {
        // ---------------- init path (ported k_init_pre) ----------------------
        int bk = blockIdx.x - BB * 32;
        int k = bk & (KK - 1);
        float* sh2 = ws;             // reuse smem
        float sg = 0.f, slot = 0.f;
        if (t < 64) {
            sg = expf(ls[k * 64 + t]);
            slot = mu[k * 64 + t] + sg * noise[bk * 64 + t];
            g_sigma[bk * 64 + t] = sg;
            g_slots[bk * 64 + t] = slot;
            sh2[t] = slot;
        }
        __syncthreads();
        if (t < 64) {
            int d = t, h = d >> 4;
            float m = 0.f, q = 0.f;
#pragma unroll
            for (int j = 0; j < 64; j++) { float v = sh2[j]; m += v; q += v * v; }
            m *= (1.f / 64.f);
            float var = q * (1.f / 64.f) - m * m;
            float sln = (slot - m) * rsqrtf(var + EPSF) * gsl[d] + bsl[d];
            float qd = sln * tq[((size_t)k * 64 + d) * 64 + d];
            float invden = 1.f / (sg * sg + EPSF);
            g_a[bk * 64 + d] = -0.5f * invden;
            g_bq[bk * 64 + d] = qd * invden;
            float cp = -logf(fmaxf(sg, EPSF)) - 0.5f * qd * qd * invden;
#pragma unroll
            for (int o = 1; o < 16; o <<= 1) cp += __shfl_xor_sync(0xffffffffu, cp, o);
            if ((d & 15) == 0) g_C[bk * 4 + h] = logf(mix0[k] + EPSF) + LOGPI_SUM + cp;
            g_S2[bk * 64 + d] = 0.f;
            if (d < 4) g_A[bk * 4 + d] = 0.f;
#pragma unroll
            for (int i = 0; i < 4; i++) g_T[bk * 256 + i * 64 + d] = 0.f;
        }
        return;
    }

    // ---------------- LN + keys path -----------------------------------------
    int b = blockIdx.x >> 5;
    int n0 = (blockIdx.x & 31) << 7;
    {
        const float4* xg = (const float4*)(emb + ((size_t)b * NN + n0) * 64);
#pragma unroll
        for (int r = 0; r < 16; r++) {
            int idx = t + r * 128;
            int n = idx & 127, e4 = idx >> 7;
            float4 v = xg[n * 16 + e4];
            int e0 = e4 << 2;
            xs[(e0 + 0) * 128 + n] = v.x;
            xs[(e0 + 1) * 128 + n] = v.y;
            xs[(e0 + 2) * 128 + n] = v.z;
            xs[(e0 + 3) * 128 + n] = v.w;
        }
    }
    __syncthreads();
    {
        float s = 0.f, q = 0.f;
#pragma unroll 8
        for (int e = 0; e < 64; e++) { float v = xs[e * 128 + t]; s += v; q += v * v; }
        float m = s * (1.f / 64.f);
        float var = q * (1.f / 64.f) - m * m;
        float rr = rsqrtf(var + EPSF);
        float* gx = g_x + ((size_t)b * NN + n0 + t) * 64;
#pragma unroll 4
        for (int e = 0; e < 64; e += 4) {
            float4 o;
            o.x = (xs[(e + 0) * 128 + t] - m) * rr * lng[e + 0] + lnb[e + 0];
            o.y = (xs[(e + 1) * 128 + t] - m) * rr * lng[e + 1] + lnb[e + 1];
            o.z = (xs[(e + 2) * 128 + t] - m) * rr * lng[e + 2] + lnb[e + 2];
            o.w = (xs[(e + 3) * 128 + t] - m) * rr * lng[e + 3] + lnb[e + 3];
            xs[(e + 0) * 128 + t] = o.x;
            xs[(e + 1) * 128 + t] = o.y;
            xs[(e + 2) * 128 + t] = o.z;
            xs[(e + 3) * 128 + t] = o.w;
            *(float4*)&gx[e] = o;
        }
    }
    int tx = t & 7, ty = t >> 3;
    int d0 = tx << 3;     // 0..56
    int nr = ty << 3;     // 0..120
    for (int k = 0; k < KK; k++) {
        __syncthreads();
        const float4* wg = (const float4*)(tk + (size_t)k * 4096);
#pragma unroll
        for (int r = 0; r < 8; r++)
            ((float4*)ws)[t + r * 128] = wg[t + r * 128];
        __syncthreads();
        ull acc[8][4];
#pragma unroll
        for (int n = 0; n < 8; n++)
#pragma unroll
            for (int p = 0; p < 4; p++) acc[n][p] = 0ull;
#pragma unroll 8
        for (int e = 0; e < 64; e++) {
            F4U wa; wa.v = *(const float4*)&ws[e * 64 + d0];
            F4U wb; wb.v = *(const float4*)&ws[e * 64 + d0 + 4];
            F4U xa; xa.v = *(const float4*)&xs[e * 128 + nr];
            F4U xb; xb.v = *(const float4*)&xs[e * 128 + nr + 4];
#pragma unroll
            for (int n = 0; n < 8; n++) {
                float xv = (n < 4) ? xa.s[n] : xb.s[n - 4];
                ull x2 = pk2(xv, xv);
                fma2(acc[n][0], x2, wa.u[0]);
                fma2(acc[n][1], x2, wa.u[1]);
                fma2(acc[n][2], x2, wb.u[0]);
                fma2(acc[n][3], x2, wb.u[1]);
            }
        }
        size_t o0 = (((size_t)b * NN + n0 + nr) * KK + k) * 64 + d0;
#pragma unroll
        for (int n = 0; n < 8; n++) {
            F4U oa, ob;
            oa.u[0] = acc[n][0]; oa.u[1] = acc[n][1];
            ob.u[0] = acc[n][2]; ob.u[1] = acc[n][3];
            *(float4*)&g_keys[o0 + (size_t)n * 512]     = oa.v;
            *(float4*)&g_keys[o0 + (size_t)n * 512 + 4] = ob.v;
        }
    }
}

// ---------------- fused attention pass (R6-best + LRU-friendly reversal) ----
__global__ __launch_bounds__(256, 2) void k_pass(float* __restrict__ attn_out,
                                                 int last, int rev) {
    __shared__ float4 xs[2048];       // [n][e/4]  32 KB
    __shared__ float attn_s[4096];    // [n][kh]   16 KB
    int bidx = rev ? ((int)gridDim.x - 1 - (int)blockIdx.x) : (int)blockIdx.x;
    int b = bidx >> 5;
    int n0 = (bidx & 31) << 7;
    int t = threadIdx.x, w = t >> 5, lane = t & 31;
    int bk = b * KK + (lane >> 2);
    int h = lane & 3;
    F4U a4[4], b4[4];
#pragma unroll
    for (int i = 0; i < 4; i++) {
        a4[i].v = *(const float4*)&g_a[bk * 64 + h * 16 + i * 4];
        b4[i].v = *(const float4*)&g_bq[bk * 64 + h * 16 + i * 4];
    }
    float C = g_C[bk * 4 + h];
    for (int i = t; i < 2048; i += 256)
        xs[i] = ((const float4*)g_x)[((size_t)b * NN + n0) * 16 + i];
    __syncthreads();

    F4U S2a[4];
#pragma unroll
    for (int j = 0; j < 4; j++) { S2a[j].u[0] = 0ull; S2a[j].u[1] = 0ull; }
    float Aacc = 0.f;
    float* aout = attn_out + (size_t)bk * NN * 4 + h;
    const float4* kbase = ((const float4*)g_keys) + ((size_t)b * NN + n0) * 128 + lane * 4;

    F4U q0, q1, q2, q3;
    { const float4* kp = kbase + (size_t)(w * 16) * 128;
      q0.v = kp[0]; q1.v = kp[1]; q2.v = kp[2]; q3.v = kp[3]; }
#pragma unroll 2
    for (int ni = 0; ni < 16; ni++) {
        int nl = w * 16 + ni;
        ull kp8[8] = {q0.u[0], q0.u[1], q1.u[0], q1.u[1], q2.u[0], q2.u[1], q3.u[0], q3.u[1]};
        if (ni < 15) {
            const float4* kp = kbase + (size_t)(nl + 1) * 128;
            q0.v = kp[0]; q1.v = kp[1]; q2.v = kp[2]; q3.v = kp[3];
        }
        ull lgp = 0ull;
#pragma unroll
        for (int j = 0; j < 8; j++) {
            ull tmp = fma2r(kp8[j], a4[j >> 1].u[j & 1], b4[j >> 1].u[j & 1]);
            lgp = fma2r(kp8[j], tmp, lgp);
        }
        F4U lgu; lgu.u[0] = lgp;
        float lg = C + lgu.s[0] + lgu.s[1];
        float mm = lg;
        mm = fmaxf(mm, __shfl_xor_sync(0xffffffffu, mm, 4));
        mm = fmaxf(mm, __shfl_xor_sync(0xffffffffu, mm, 8));
        mm = fmaxf(mm, __shfl_xor_sync(0xffffffffu, mm, 16));
        float ex = __expf(lg - mm);
        float ss = ex;
        ss += __shfl_xor_sync(0xffffffffu, ss, 4);
        ss += __shfl_xor_sync(0xffffffffu, ss, 8);
        ss += __shfl_xor_sync(0xffffffffu, ss, 16);
        float attn = __fdividef(ex, ss) + EPSF;
        attn_s[nl * 32 + lane] = attn;
        if (last) aout[(size_t)(n0 + nl) * 4] = attn;
        Aacc += attn;
        ull attn2 = pk2(attn, attn);
#pragma unroll
        for (int j = 0; j < 8; j++) {
            ull ak = mul2(attn2, kp8[j]);
            S2a[j >> 1].u[j & 1] = fma2r(ak, kp8[j], S2a[j >> 1].u[j & 1]);
        }
    }
    __syncthreads();

    {
        int kh = t >> 3, et = t & 7;
        ull Tl[4] = {0ull, 0ull, 0ull, 0ull};
        const float* ap = attn_s + kh;
        const float4* xp = xs + et * 2;
#pragma unroll 4
        for (int n = 0; n < 128; n++) {
            float at = ap[n * 32];
            ull at2 = pk2(at, at);
            F4U xa; xa.v = xp[n * 16];
            F4U xb; xb.v = xp[n * 16 + 1];
            Tl[0] = fma2r(at2, xa.u[0], Tl[0]);
            Tl[1] = fma2r(at2, xa.u[1], Tl[1]);
            Tl[2] = fma2r(at2, xb.u[0], Tl[2]);
            Tl[3] = fma2r(at2, xb.u[1], Tl[3]);
        }
        int k2 = kh >> 2, h2 = kh & 3;
        float* gp = &g_T[(size_t)(b * KK + k2) * 256 + h2 * 64 + et * 8];
        F4U o0, o1;
        o0.u[0] = Tl[0]; o0.u[1] = Tl[1];
        o1.u[0] = Tl[2]; o1.u[1] = Tl[3];
#pragma unroll
        for (int j = 0; j < 4; j++) atomicAdd(gp + j, o0.s[j]);
#pragma unroll
        for (int j = 0; j < 4; j++) atomicAdd(gp + 4 + j, o1.s[j]);
    }

    __syncthreads();
    float* redf = attn_s;
#define SIDX(ww, j) ((ww) * 544 + lane * 17 + (j))
    if (w >= 4) {
#pragma unroll
        for (int j = 0; j < 16; j++) redf[SIDX(w - 4, j)] = S2a[j >> 2].s[j & 3];
        redf[SIDX(w - 4, 16)] = Aacc;
    }
    __syncthreads();
    if (w < 4) {
#pragma unroll
        for (int j = 0; j < 16; j++) S2a[j >> 2].s[j & 3] += redf[SIDX(w, j)];
        Aacc += redf[SIDX(w, 16)];
    }
    __syncthreads();
    if (w == 2 || w == 3) {
#pragma unroll
        for (int j = 0; j < 16; j++) redf[SIDX(w - 2, j)] = S2a[j >> 2].s[j & 3];
        redf[SIDX(w - 2, 16)] = Aacc;
    }
    __syncthreads();
    if (w < 2) {
#pragma unroll
        for (int j = 0; j < 16; j++) S2a[j >> 2].s[j & 3] += redf[SIDX(w, j)];
        Aacc += redf[SIDX(w, 16)];
    }
    __syncthreads();
    if (w == 1) {
#pragma unroll
        for (int j = 0; j < 16; j++) redf[SIDX(0, j)] = S2a[j >> 2].s[j & 3];
        redf[SIDX(0, 16)] = Aacc;
    }
    __syncthreads();
    if (w == 0) {
#pragma unroll
        for (int j = 0; j < 16; j++)
            atomicAdd(&g_S2[(size_t)b * 512 + lane * 16 + j],
                      S2a[j >> 2].s[j & 3] + redf[SIDX(0, j)]);
        atomicAdd(&g_A[b * 32 + lane], Aacc + redf[SIDX(0, 16)]);
    }
}

// ---------------- slot update: 256 threads, hoisted staging (R15) -----------
__global__ __launch_bounds__(256) void k_upd(
        const float* __restrict__ tk, const float* __restrict__ tv,
        const float* __restrict__ wih, const float* __restrict__ whh,
        const float* __restrict__ bih, const float* __restrict__ bhh,
        const float* __restrict__ w1, const float* __restrict__ b1,
        const float* __restrict__ w2, const float* __restrict__ b2,
        const float* __restrict__ gff, const float* __restrict__ bff,
        const float* __restrict__ tq, const float* __restrict__ gsl,
        const float* __restrict__ bsl,
        const float* __restrict__ noisef, float* __restrict__ out_slots, int last) {
    int bk = blockIdx.x;
    int k = bk & (KK - 1);
    int t = threadIdx.x;
    int d = t & 63, quar = t >> 6;
    int h = d >> 4;
    __shared__ float Wt[24576];
    __shared__ float W1s[16384];
    __shared__ float Tsh[4][64], Ash[4];
    __shared__ float pu[4][64], ps1[4][64];
    __shared__ float ush[64], hsh[64];
    __shared__ float gsh[6][64];
    __shared__ float sh[64], presh[64], h1sh[256], pw2[4][64], osh[64];

    for (int idx = t; idx < 384; idx += 256) {
        int s = idx >= 192;
        int row = idx - s * 192;
        const float4* src = (const float4*)((s ? whh : wih) + (size_t)row * 64);
        float* dst = Wt + s * 12288 + row;
#pragma unroll
        for (int r = 0; r < 16; r++) {
            float4 v = src[r];
            dst[(4 * r + 0) * 192] = v.x;
            dst[(4 * r + 1) * 192] = v.y;
            dst[(4 * r + 2) * 192] = v.z;
            dst[(4 * r + 3) * 192] = v.w;
        }
    }
    {
        const float4* src = (const float4*)(w1 + (size_t)t * 64);
        float* dst = W1s + t;
#pragma unroll
        for (int r = 0; r < 16; r++) {
            float4 v = src[r];
            dst[(4 * r + 0) * 256] = v.x;
            dst[(4 * r + 1) * 256] = v.y;
            dst[(4 * r + 2) * 256] = v.z;
            dst[(4 * r + 3) * 256] = v.w;
        }
    }
    if (t < 256) Tsh[t >> 6][t & 63] = g_T[bk * 256 + t];
    if (t < 4) Ash[t] = g_A[bk * 4 + t];
    if (t >= 64 && t < 128) hsh[d] = g_slots[bk * 64 + d];
    __syncthreads();
    float Nk = Ash[0] + Ash[1] + Ash[2] + Ash[3];
    {
        float u = 0.f, s1 = 0.f;
        int e0 = quar * 16;
#pragma unroll
        for (int e = e0; e < e0 + 16; e++) {
            float tvv = Tsh[h][e];
            u  = fmaf(tvv, tv[((size_t)k * 64 + e) * 64 + d], u);
            s1 = fmaf(tvv, tk[((size_t)k * 64 + e) * 64 + d], s1);
        }
        pu[quar][d] = u; ps1[quar][d] = s1;
    }
    __syncthreads();
    float sigma_d = 0.f;
    if (t < 64) {
        float u = pu[0][d] + pu[1][d] + pu[2][d] + pu[3][d];
        float s1 = ps1[0][d] + ps1[1][d] + ps1[2][d] + ps1[3][d];
        float invNk = 1.f / Nk;
        u *= (invNk + EPSF);
        float sig2 = fmaxf(g_S2[bk * 64 + d] - 2.f * u * s1 + u * u * Ash[h], 0.f);
        sigma_d = sqrtf(sig2 * invNk) + EPSF;
        g_sigma[bk * 64 + d] = sigma_d;
        ush[d] = u;
    }
    __syncthreads();
    {
        int g1i = t;
        int gA = g1i >> 6, dA = g1i & 63;
        const float* viA = (gA < 3) ? ush : hsh;
        const float* WA = Wt + (gA < 3 ? 0 : 12288) + (gA % 3) * 64 + dA;
        float accA = (gA < 3 ? bih : bhh)[(gA % 3) * 64 + dA];
        if (t < 128) {
            int g2i = t + 256;
            int gB = g2i >> 6, dB = g2i & 63;
            const float* viB = (gB < 3) ? ush : hsh;
            const float* WB = Wt + (gB < 3 ? 0 : 12288) + (gB % 3) * 64 + dB;
            float accB = (gB < 3 ? bih : bhh)[(gB % 3) * 64 + dB];
#pragma unroll 8
            for (int e = 0; e < 64; e++) {
                accA = fmaf(viA[e], WA[e * 192], accA);
                accB = fmaf(viB[e], WB[e * 192], accB);
            }
            gsh[gB][dB] = accB;
        } else {
#pragma unroll 8
            for (int e = 0; e < 64; e++)
                accA = fmaf(viA[e], WA[e * 192], accA);
        }
        gsh[gA][dA] = accA;
    }
    __syncthreads();
    float snew = 0.f;
    if (t < 64) {
        float r = 1.f / (1.f + expf(-(gsh[0][d] + gsh[3][d])));
        float z = 1.f / (1.f + expf(-(gsh[1][d] + gsh[4][d])));
        float nn2 = tanhf(gsh[2][d] + r * gsh[5][d]);
        snew = (1.f - z) * nn2 + z * hsh[d];
        sh[d] = snew;
    }
    {
        int row = t & 63, q2 = t >> 6;
        const float4* src = (const float4*)(w2 + (size_t)row * 256 + q2 * 64);
        float* dst = Wt + row;
#pragma unroll
        for (int r = 0; r < 16; r++) {
            float4 v = src[r];
            dst[(q2 * 64 + 4 * r + 0) * 64] = v.x;
            dst[(q2 * 64 + 4 * r + 1) * 64] = v.y;
            dst[(q2 * 64 + 4 * r + 2) * 64] = v.z;
            dst[(q2 * 64 + 4 * r + 3) * 64] = v.w;
        }
    }
    __syncthreads();
    if (t < 64) {
        float m = 0.f, qq = 0.f;
#pragma unroll
        for (int j = 0; j < 64; j++) { float v = sh[j]; m += v; qq += v * v; }
        m *= (1.f / 64.f);
        float var = qq * (1.f / 64.f) - m * m;
        presh[d] = (snew - m) * rsqrtf(var + EPSF) * gff[d] + bff[d];
    }
    __syncthreads();
    {
        float acc = b1[t];
        const float* wr = W1s + t;
#pragma unroll 8
        for (int e = 0; e < 64; e++) acc = fmaf(presh[e], wr[e * 256], acc);
        h1sh[t] = fmaxf(acc, 0.f);
    }
    __syncthreads();
    {
        float o = 0.f;
        int j0 = quar * 64;
#pragma unroll 8
        for (int j = j0; j < j0 + 64; j++) o = fmaf(h1sh[j], Wt[j * 64 + d], o);
        pw2[quar][d] = o;
    }
    __syncthreads();
    if (t < 64) {
        float o = sh[d] + b2[d] + pw2[0][d] + pw2[1][d] + pw2[2][d] + pw2[3][d];
        g_slots[bk * 64 + d] = o;
        if (last) out_slots[bk * 64 + d] = o + sigma_d * noisef[bk * 64 + d];
        osh[d] = o;
    }
    __syncthreads();
    if (!last) {
        if (t < 64) {
            float m = 0.f, qq = 0.f;
#pragma unroll
            for (int j = 0; j < 64; j++) { float v = osh[j]; m += v; qq += v * v; }
            m *= (1.f / 64.f);
            float var = qq * (1.f / 64.f) - m * m;
            float sln = (osh[d] - m) * rsqrtf(var + EPSF) * gsl[d] + bsl[d];
            float qd = sln * tq[((size_t)k * 64 + d) * 64 + d];
            float invden = 1.f / (sigma_d * sigma_d + EPSF);
            g_a[bk * 64 + d]  = -0.5f * invden;
            g_bq[bk * 64 + d] = qd * invden;
            float cp = -logf(fmaxf(sigma_d, EPSF)) - 0.5f * qd * qd * invden;
#pragma unroll
            for (int o = 1; o < 16; o <<= 1) cp += __shfl_xor_sync(0xffffffffu, cp, o);
            if ((d & 15) == 0)
                g_C[bk * 4 + h] = logf(Nk * (1.f / (float)NN) + EPSF) + LOGPI_SUM + cp;
            g_S2[bk * 64 + d] = 0.f;
            if (d < 4) g_A[bk * 4 + d] = 0.f;
        }
        if (t < 256) g_T[bk * 256 + t] = 0.f;
    }
}

// ---------------- launch ----------------------------------------------------
extern "C" void kernel_launch(void* const* d_in, const int* in_sizes, int n_in,
                              void* d_out, int out_size) {
    const float* emb   = (const float*)d_in[0];
    const float* mu    = (const float*)d_in[1];
    const float* ls    = (const float*)d_in[2];
    const float* mix0  = (const float*)d_in[3];
    const float* tk    = (const float*)d_in[4];
    const float* tq    = (const float*)d_in[5];
    const float* tv    = (const float*)d_in[6];
    const float* wih   = (const float*)d_in[7];
    const float* whh   = (const float*)d_in[8];
    const float* bih   = (const float*)d_in[9];
    const float* bhh   = (const float*)d_in[10];
    const float* w1    = (const float*)d_in[11];
    const float* b1    = (const float*)d_in[12];
    const float* w2    = (const float*)d_in[13];
    const float* b2    = (const float*)d_in[14];
    const float* ling  = (const float*)d_in[15];
    const float* linb  = (const float*)d_in[16];
    const float* lslg  = (const float*)d_in[17];
    const float* lslb  = (const float*)d_in[18];
    const float* lffg  = (const float*)d_in[19];
    const float* lffb  = (const float*)d_in[20];
    const float* nzi   = (const float*)d_in[21];
    const float* nzf   = (const float*)d_in[22];

    float* out_slots = (float*)d_out;                  // [B,K,D]
    float* out_attn  = (float*)d_out + BB * KK * DD;   // [B,K,N,H]

    k_lnkeys<<<BB * 32 + BB * KK, 128>>>(emb, ling, linb, tk,
                                         mu, ls, mix0, nzi, tq, lslg, lslb);
    for (int it = 0; it < 3; it++) {
        int last = (it == 2);
        int rev = (it == 1);          // alternate scan direction: LRU-friendly
        k_pass<<<BB * 32, 256>>>(out_attn, last, rev);
        k_upd<<<BB * KK, 256>>>(tk, tv, wih, whh, bih, bhh, w1, b1, w2, b2,
                                lffg, lffb, tq, lslg, lslb, nzf, out_slots, last);
    }
}